// round 8
// baseline (speedup 1.0000x reference)
#include <cuda_runtime.h>
#include <cuda_bf16.h>
#include <cstdint>

// ============================================================================
// Hyperbolic averaged Hausdorff loss via tensor-core mma.sync (bf16).
// (build targets plain sm_103: tcgen05 unavailable; legacy HMMA path)
//
// R8: K=48 (pure dot GEMM, bf16 hi/lo split: acc = xh.yh + xl.yh + xh.yl),
// norms applied in the epilogue with scalar FMAs:
//   t_ij = (xn+yn-2dot)*invy = fma(dot, -2iy_j, fma(xn_i, iy_j, yn_j*iy_j))
//   s_ij = (xn+yn-2dot)*invx = fma(dot, -2ix_i, fma(yn_j, ix_i, xn_i*ix_i))
// Per-point params float4: (n2, inv, -2inv, n2*inv).
// Persistent-A sweep (8 B-tiles, cp.async double buffer, 1 barrier/tile),
// col mins via reduce-scatter shuffles -> direct lane atomics.
// ============================================================================

#define NPTS 16384
#define TILES_PER_SWEEP 8

__device__ float4 g_px[NPTS], g_py[NPTS];
__device__ int    g_rowmin[NPTS], g_colmin[NPTS];
__device__ float  g_part[128];
__device__ int    g_done;
__device__ __nv_bfloat16 g_A[NPTS * 48];
__device__ __nv_bfloat16 g_B[NPTS * 48];

__device__ __forceinline__ uint32_t smem_u32(const void* p) {
    uint32_t a;
    asm("{ .reg .u64 t; cvta.to.shared.u64 t, %1; cvt.u32.u64 %0, t; }"
        : "=r"(a) : "l"(p));
    return a;
}
#define SMEM_SWZ(o) ((o) ^ ((((o) >> 3) & 0x70)))

#define CPASYNC16(dst, src) \
    asm volatile("cp.async.cg.shared.global [%0], [%1], 16;" \
                 :: "r"(dst), "l"(src))
#define CPCOMMIT() asm volatile("cp.async.commit_group;")
#define CPWAIT0()  asm volatile("cp.async.wait_group 0;")

#define LDSM4(r, addr)                                                      \
    asm volatile("ldmatrix.sync.aligned.m8n8.x4.shared.b16 "                \
                 "{%0,%1,%2,%3}, [%4];"                                     \
                 : "=r"((r)[0]), "=r"((r)[1]), "=r"((r)[2]), "=r"((r)[3])   \
                 : "r"(addr))

#define MMA16816(d, a, b0, b1)                                              \
    asm volatile("mma.sync.aligned.m16n8k16.row.col.f32.bf16.bf16.f32 "     \
                 "{%0,%1,%2,%3}, {%4,%5,%6,%7}, {%8,%9}, {%0,%1,%2,%3};"    \
                 : "+f"((d)[0]), "+f"((d)[1]), "+f"((d)[2]), "+f"((d)[3])   \
                 : "r"((a)[0]), "r"((a)[1]), "r"((a)[2]), "r"((a)[3]),      \
                   "r"(b0), "r"(b1))

// ---------------------------------------------------------------- smem layout
#define SM_A    0                       // 16384   (128 rows x 128B pitch)
#define SM_B    16384                   // 2 x 16384 -> ends 49152
#define SM_PY   49152                   // 1024 x float4 = 16384
#define SM_ROW  65536                   // 2 x 128 x f32 = 1024
#define SM_TOT  66560

// ---------------------------------------------------------------- prep kernel
union BU { __nv_bfloat16 b; unsigned short u; };
__device__ __forceinline__ unsigned short bfu(float x) {
    BU t; t.b = __float2bfloat16(x); return t.u;
}
__device__ __forceinline__ float bff(unsigned short u) {
    BU t; t.u = u; return __bfloat162float(t.b);
}

__device__ __forceinline__ void split_store(const float* src, int idx,
                                            __nv_bfloat16* dst, bool isA,
                                            float4* par, int* mn) {
    float v[16];
    const float4* p = (const float4*)(src + (size_t)idx * 16);
    float4 q0 = p[0], q1 = p[1], q2 = p[2], q3 = p[3];
    v[0]=q0.x; v[1]=q0.y; v[2]=q0.z; v[3]=q0.w;
    v[4]=q1.x; v[5]=q1.y; v[6]=q1.z; v[7]=q1.w;
    v[8]=q2.x; v[9]=q2.y; v[10]=q2.z; v[11]=q2.w;
    v[12]=q3.x; v[13]=q3.y; v[14]=q3.z; v[15]=q3.w;
    float s = 0.f;
#pragma unroll
    for (int d = 0; d < 16; d++) s += v[d] * v[d];
    float inv = 1.0f / (1.0f - s);
    par[idx] = make_float4(s, inv, -2.0f * inv, s * inv);
    mn[idx]  = 0x7f800000;

    unsigned short hi[16], lo[16];
#pragma unroll
    for (int d = 0; d < 16; d++) {
        hi[d] = bfu(v[d]);
        lo[d] = bfu(v[d] - bff(hi[d]));
    }
    // A: [hi | lo | hi], B: [hi | hi | lo]  (K=48)
    uint32_t w[24];
#pragma unroll
    for (int k = 0; k < 8; k++) {
        uint32_t hp = (uint32_t)hi[2*k] | ((uint32_t)hi[2*k+1] << 16);
        uint32_t lp = (uint32_t)lo[2*k] | ((uint32_t)lo[2*k+1] << 16);
        w[k]      = hp;
        w[8 + k]  = isA ? lp : hp;
        w[16 + k] = isA ? hp : lp;
    }
    uint4* d4 = (uint4*)(dst + (size_t)idx * 48);
#pragma unroll
    for (int c = 0; c < 6; c++)
        d4[c] = make_uint4(w[4*c], w[4*c+1], w[4*c+2], w[4*c+3]);
}

__global__ void prep_kernel(const float* __restrict__ X,
                            const float* __restrict__ Y, int N, int M) {
    int b = blockIdx.x;
    if (b == 0 && threadIdx.x == 0) g_done = 0;
    if (b < 64) {
        int idx = b * 256 + threadIdx.x;
        if (idx < N) split_store(X, idx, g_A, true,  g_px, g_rowmin);
    } else {
        int idx = (b - 64) * 256 + threadIdx.x;
        if (idx < M) split_store(Y, idx, g_B, false, g_py, g_colmin);
    }
}

// ---------------------------------------------------------------- pair kernel
__global__ void __launch_bounds__(256, 2) pair_mma_kernel() {
    extern __shared__ __align__(16) char smem[];
    const uint32_t sb = smem_u32(smem);

    const int tid  = threadIdx.x;
    const int wid  = tid >> 5;
    const int lane = tid & 31;
    const int i0   = blockIdx.y * 128;
    const int jc0  = blockIdx.x * 1024;

    const int wr = wid & 3;
    const int wc = wid >> 2;
    const int lr = lane & 15;
    const int lc = lane >> 4;
    const float INF = __int_as_float(0x7f800000);

    // 16B-chunk mapping for a 128x96B tile (768 chunks, 3 per thread)
    uint32_t tswz[3];
    uint32_t tgof[3];
#pragma unroll
    for (int q = 0; q < 3; q++) {
        int c = tid + q * 256;
        int r = c / 6, cl = c - 6 * r;
        tswz[q] = SMEM_SWZ(r * 128 + cl * 16);
        tgof[q] = c * 16;
    }

    // ---- prologue: async-copy A tile + B tile 0 + py table
    {
        const char* Ag = (const char*)g_A + (size_t)i0 * 96;
        const char* Bg = (const char*)g_B + (size_t)jc0 * 96;
#pragma unroll
        for (int q = 0; q < 3; q++) {
            CPASYNC16(sb + SM_A + tswz[q], Ag + tgof[q]);
            CPASYNC16(sb + SM_B + tswz[q], Bg + tgof[q]);
        }
        const char* Pg = (const char*)(g_py + jc0);
#pragma unroll
        for (int q = 0; q < 4; q++) {
            uint32_t o = (tid + q * 256) * 16;
            CPASYNC16(sb + SM_PY + o, Pg + o);
        }
        CPCOMMIT();
    }

    // per-row constants (LDG float4, overlaps the cp.async wait)
    float xnv[4], ixv[4], axv[4], bxv[4];
#pragma unroll
    for (int mt = 0; mt < 2; mt++)
#pragma unroll
        for (int rr = 0; rr < 2; rr++) {
            int k = 2 * mt + rr;
            float4 p = g_px[i0 + 32*wr + 16*mt + 8*rr + (lane >> 2)];
            xnv[k] = p.x; ixv[k] = p.y; axv[k] = p.z; bxv[k] = p.w;
        }

    CPWAIT0();
    __syncthreads();

    // ---- A fragments once per sweep (3 k-steps)
    uint32_t afr[3][2][4];
#pragma unroll
    for (int ks = 0; ks < 3; ks++)
#pragma unroll
        for (int mt = 0; mt < 2; mt++) {
            int row = 32*wr + 16*mt + lr;
            LDSM4(afr[ks][mt], sb + SM_A + SMEM_SWZ(row*128 + ks*32 + lc*16));
        }

    // prefetch B tile 1
    {
        const char* Bg = (const char*)g_B + (size_t)(jc0 + 128) * 96;
        uint32_t d = sb + SM_B + 16384;
#pragma unroll
        for (int q = 0; q < 3; q++) CPASYNC16(d + tswz[q], Bg + tgof[q]);
        CPCOMMIT();
    }

    const float4* sPY = (const float4*)(smem + SM_PY);
    float rmin[4] = {INF, INF, INF, INF};

    const int b16 = (lane >> 4) & 1;
    const int b8  = (lane >> 3) & 1;
    const int b4  = (lane >> 2) & 1;
    const int ownCol = 8 * (2 * b16 + b8) + 2 * (lane & 3) + b4;

#pragma unroll 1
    for (int t = 0; t < TILES_PER_SWEEP; t++) {
        if (t > 0) {
            CPWAIT0();
            __syncthreads();
            if (t + 1 < TILES_PER_SWEEP) {
                const char* Bg =
                    (const char*)g_B + (size_t)(jc0 + (t + 1) * 128) * 96;
                uint32_t d = sb + SM_B + ((t + 1) & 1) * 16384;
#pragma unroll
                for (int q = 0; q < 3; q++) CPASYNC16(d + tswz[q], Bg + tgof[q]);
                CPCOMMIT();
            }
        }

        const uint32_t sBb = sb + SM_B + (t & 1) * 16384;
        const int jt = t * 128;

#pragma unroll
        for (int h = 0; h < 2; h++) {
            float acc[2][4][4];
#pragma unroll
            for (int mt = 0; mt < 2; mt++)
#pragma unroll
                for (int nt = 0; nt < 4; nt++)
#pragma unroll
                    for (int e = 0; e < 4; e++) acc[mt][nt][e] = 0.0f;

#pragma unroll
            for (int ks = 0; ks < 3; ks++) {
                uint32_t b[2][4];
#pragma unroll
                for (int np = 0; np < 2; np++) {
                    int row = 64*wc + 32*h + 16*np + lr;
                    LDSM4(b[np], sBb + SMEM_SWZ(row*128 + ks*32 + lc*16));
                }
#pragma unroll
                for (int mt = 0; mt < 2; mt++)
#pragma unroll
                    for (int nt = 0; nt < 4; nt++) {
                        int np = nt >> 1, od = nt & 1;
                        MMA16816(acc[mt][nt], afr[ks][mt], b[np][od], b[np][od+2]);
                    }
            }

            // ---- epilogue: pre-FMAs + fma/min per element
            float v[8];
#pragma unroll
            for (int k = 0; k < 8; k++) v[k] = INF;

#pragma unroll
            for (int nt = 0; nt < 4; nt++) {
                int j = jt + 64*wc + 32*h + 8*nt + 2*(lane & 3);
                float4 f0 = sPY[j], f1 = sPY[j + 1];  // (yn, iy, -2iy, yn*iy)
                float py0[4], py1[4], px0[4], px1[4];
#pragma unroll
                for (int r = 0; r < 4; r++) {
                    py0[r] = fmaf(xnv[r], f0.y, f0.w);
                    py1[r] = fmaf(xnv[r], f1.y, f1.w);
                    px0[r] = fmaf(f0.x, ixv[r], bxv[r]);
                    px1[r] = fmaf(f1.x, ixv[r], bxv[r]);
                }
#pragma unroll
                for (int mt = 0; mt < 2; mt++) {
                    const float* c = acc[mt][nt];
                    int r0 = 2*mt, r1 = 2*mt + 1;
                    float t0 = fmaf(c[0], f0.z, py0[r0]);
                    float t1 = fmaf(c[1], f1.z, py1[r0]);
                    rmin[r0] = fminf(rmin[r0], fminf(t0, t1));
                    float t2 = fmaf(c[2], f0.z, py0[r1]);
                    float t3 = fmaf(c[3], f1.z, py1[r1]);
                    rmin[r1] = fminf(rmin[r1], fminf(t2, t3));

                    float s0 = fmaf(c[0], axv[r0], px0[r0]);
                    float s2 = fmaf(c[2], axv[r1], px0[r1]);
                    v[2*nt]   = fminf(v[2*nt],   fminf(s0, s2));
                    float s1 = fmaf(c[1], axv[r0], px1[r0]);
                    float s3 = fmaf(c[3], axv[r1], px1[r1]);
                    v[2*nt+1] = fminf(v[2*nt+1], fminf(s1, s3));
                }
            }

            // ---- reduce-scatter col mins across the 8 duplicate lanes
#pragma unroll
            for (int q = 0; q < 4; q++) {
                float x = b16 ? v[q] : v[q + 4];
                float r = __shfl_xor_sync(0xffffffffu, x, 16);
                if (b16) v[q + 4] = fminf(v[q + 4], r);
                else     v[q]     = fminf(v[q], r);
            }
#pragma unroll
            for (int g = 0; g < 8; g += 4)
#pragma unroll
                for (int q = 0; q < 2; q++) {
                    float x = b8 ? v[g + q] : v[g + q + 2];
                    float r = __shfl_xor_sync(0xffffffffu, x, 8);
                    if (b8) v[g + q + 2] = fminf(v[g + q + 2], r);
                    else    v[g + q]     = fminf(v[g + q], r);
                }
#pragma unroll
            for (int g = 0; g < 8; g += 2) {
                float x = b4 ? v[g] : v[g + 1];
                float r = __shfl_xor_sync(0xffffffffu, x, 4);
                if (b4) v[g + 1] = fminf(v[g + 1], r);
                else    v[g]     = fminf(v[g], r);
            }
            float owned = b16 ? (b8 ? (b4 ? v[7] : v[6]) : (b4 ? v[5] : v[4]))
                              : (b8 ? (b4 ? v[3] : v[2]) : (b4 ? v[1] : v[0]));
            atomicMin(&g_colmin[jc0 + jt + 64*wc + 32*h + ownCol],
                      __float_as_int(fmaxf(owned, 0.0f)));
        }
    }

    // ---- sweep epilogue: row mins
    float* rowp = (float*)(smem + SM_ROW);       // [2][128]
#pragma unroll
    for (int k = 0; k < 4; k++) {
        float v = rmin[k];
        v = fminf(v, __shfl_xor_sync(0xffffffffu, v, 1));
        v = fminf(v, __shfl_xor_sync(0xffffffffu, v, 2));
        if ((lane & 3) == 0)
            rowp[wc*128 + 32*wr + 16*(k >> 1) + 8*(k & 1) + (lane >> 2)] = v;
    }
    __syncthreads();
    if (tid < 128) {
        float rv = fminf(rowp[tid], rowp[128 + tid]);
        atomicMin(&g_rowmin[i0 + tid], __float_as_int(fmaxf(rv, 0.0f)));
    }
}

// ---------------------------------------------------------------- finalize
__global__ void finalize_kernel(int N, int M, float* out) {
    __shared__ float red[256];
    __shared__ int   lastFlag;
    int  b     = blockIdx.x;
    bool isRow = (b < 64);
    int  idx   = (isRow ? b : b - 64) * 256 + threadIdx.x;
    float val  = 0.0f;
    int   lim  = isRow ? N : M;
    if (idx < lim) {
        float m   = fmaxf(__int_as_float(isRow ? g_rowmin[idx] : g_colmin[idx]),
                          0.0f);
        float inv = isRow ? g_px[idx].y : g_py[idx].y;
        float u   = fmaf(2.0f * m, inv, 1.0f);
        val       = logf(u + sqrtf(fmaxf(u * u - 1.0f, 0.0f)));
    }
    red[threadIdx.x] = val;
    __syncthreads();
    for (int s = 128; s > 0; s >>= 1) {
        if (threadIdx.x < s) red[threadIdx.x] += red[threadIdx.x + s];
        __syncthreads();
    }
    if (threadIdx.x == 0) {
        g_part[b] = red[0] * (isRow ? 1.0f / (float)N : 1.0f / (float)M);
        __threadfence();
        int t = atomicAdd(&g_done, 1);
        lastFlag = (t == 127);
    }
    __syncthreads();
    if (lastFlag) {
        red[threadIdx.x] = (threadIdx.x < 128) ? g_part[threadIdx.x] : 0.0f;
        __syncthreads();
        for (int s = 128; s > 0; s >>= 1) {
            if (threadIdx.x < s) red[threadIdx.x] += red[threadIdx.x + s];
            __syncthreads();
        }
        if (threadIdx.x == 0) out[0] = red[0];
    }
}

// ---------------------------------------------------------------- launch
extern "C" void kernel_launch(void* const* d_in, const int* in_sizes, int n_in,
                              void* d_out, int out_size) {
    const float* X = (const float*)d_in[0];
    const float* Y = (const float*)d_in[1];
    int N = in_sizes[0] / 16;
    int M = in_sizes[1] / 16;

    static int configured = 0;
    if (!configured) {
        cudaFuncSetAttribute(pair_mma_kernel,
                             cudaFuncAttributeMaxDynamicSharedMemorySize,
                             SM_TOT);
        configured = 1;
    }

    prep_kernel<<<128, 256>>>(X, Y, N, M);

    dim3 grid(M / 1024, N / 128);
    pair_mma_kernel<<<grid, 256, SM_TOT>>>();

    finalize_kernel<<<128, 256>>>(N, M, (float*)d_out);
}

// round 9
// speedup vs baseline: 1.1104x; 1.1104x over previous
#include <cuda_runtime.h>
#include <cuda_bf16.h>
#include <cstdint>

// ============================================================================
// Hyperbolic averaged Hausdorff loss via tensor-core mma.sync (bf16).
// (build targets plain sm_103: tcgen05 unavailable; legacy HMMA path)
//
// K=64 norm-fold GEMM: acc_ij = dot_ij - (xn_i + yn_j)/2 (bf16 hi/lo split).
// Row-min of acc*(-2invy_j), col-min of acc*(-2invx_i); arcosh at the end.
//
// R9 = R7 + latency-shadow scheduling:
//   - one-deep software pipeline on B LDSM (load ks+1 before MMAs of ks)
//   - nyv LDS loads hoisted to the top of each column half
// ============================================================================

#define NPTS 16384
#define TILES_PER_SWEEP 8

__device__ float g_invx[NPTS], g_invy[NPTS];
__device__ int   g_rowmin[NPTS], g_colmin[NPTS];
__device__ float g_part[128];
__device__ int   g_done;
__device__ __nv_bfloat16 g_A[NPTS * 64];
__device__ __nv_bfloat16 g_B[NPTS * 64];

__device__ __forceinline__ uint32_t smem_u32(const void* p) {
    uint32_t a;
    asm("{ .reg .u64 t; cvta.to.shared.u64 t, %1; cvt.u32.u64 %0, t; }"
        : "=r"(a) : "l"(p));
    return a;
}
#define SMEM_SWZ(o) ((o) ^ ((((o) >> 3) & 0x70)))

#define CPASYNC16(dst, src) \
    asm volatile("cp.async.cg.shared.global [%0], [%1], 16;" \
                 :: "r"(dst), "l"(src))
#define CPCOMMIT() asm volatile("cp.async.commit_group;")
#define CPWAIT0()  asm volatile("cp.async.wait_group 0;")

#define LDSM4(r, addr)                                                      \
    asm volatile("ldmatrix.sync.aligned.m8n8.x4.shared.b16 "                \
                 "{%0,%1,%2,%3}, [%4];"                                     \
                 : "=r"((r)[0]), "=r"((r)[1]), "=r"((r)[2]), "=r"((r)[3])   \
                 : "r"(addr))

#define MMA16816(d, a, b0, b1)                                              \
    asm volatile("mma.sync.aligned.m16n8k16.row.col.f32.bf16.bf16.f32 "     \
                 "{%0,%1,%2,%3}, {%4,%5,%6,%7}, {%8,%9}, {%0,%1,%2,%3};"    \
                 : "+f"((d)[0]), "+f"((d)[1]), "+f"((d)[2]), "+f"((d)[3])   \
                 : "r"((a)[0]), "r"((a)[1]), "r"((a)[2]), "r"((a)[3]),      \
                   "r"(b0), "r"(b1))

// ---------------------------------------------------------------- smem layout
#define SM_A    0                       // 16384   (128 rows x 128B)
#define SM_B    16384                   // 2 x 16384 -> ends 49152
#define SM_NY   49152                   // 1024 x f32 = 4096 (-2*invy of chunk)
#define SM_ROW  53248                   // 2 x 128 x f32 = 1024
#define SM_TOT  54272

// ---------------------------------------------------------------- prep kernel
union BU { __nv_bfloat16 b; unsigned short u; };
__device__ __forceinline__ unsigned short bfu(float x) {
    BU t; t.b = __float2bfloat16(x); return t.u;
}
__device__ __forceinline__ float bff(unsigned short u) {
    BU t; t.u = u; return __bfloat162float(t.b);
}

__device__ __forceinline__ void split_store(const float* src, int idx,
                                            __nv_bfloat16* dst, bool isA,
                                            float* inv, int* mn) {
    float v[16];
    const float4* p = (const float4*)(src + (size_t)idx * 16);
    float4 q0 = p[0], q1 = p[1], q2 = p[2], q3 = p[3];
    v[0]=q0.x; v[1]=q0.y; v[2]=q0.z; v[3]=q0.w;
    v[4]=q1.x; v[5]=q1.y; v[6]=q1.z; v[7]=q1.w;
    v[8]=q2.x; v[9]=q2.y; v[10]=q2.z; v[11]=q2.w;
    v[12]=q3.x; v[13]=q3.y; v[14]=q3.z; v[15]=q3.w;
    float s = 0.f;
#pragma unroll
    for (int d = 0; d < 16; d++) s += v[d] * v[d];
    inv[idx] = 1.0f / (1.0f - s);
    mn[idx]  = 0x7f800000;

    unsigned short hi[16], lo[16];
#pragma unroll
    for (int d = 0; d < 16; d++) {
        hi[d] = bfu(v[d]);
        lo[d] = bfu(v[d] - bff(hi[d]));
    }
    uint32_t w[32];
#pragma unroll
    for (int k = 0; k < 8; k++) {
        uint32_t hp = (uint32_t)hi[2*k] | ((uint32_t)hi[2*k+1] << 16);
        uint32_t lp = (uint32_t)lo[2*k] | ((uint32_t)lo[2*k+1] << 16);
        w[k]      = hp;
        w[8 + k]  = isA ? lp : hp;
        w[16 + k] = isA ? hp : lp;
    }
    if (isA) {
        unsigned short nh = bfu(s);
        unsigned short nl = bfu(s - bff(nh));
        unsigned short one = bfu(1.0f);
        w[24] = (uint32_t)nh | ((uint32_t)nl << 16);
        w[25] = (uint32_t)one | ((uint32_t)one << 16);
    } else {
        float m = -0.5f * s;
        unsigned short mh = bfu(m);
        unsigned short ml = bfu(m - bff(mh));
        unsigned short nhalf = bfu(-0.5f);
        w[24] = (uint32_t)nhalf | ((uint32_t)nhalf << 16);
        w[25] = (uint32_t)mh | ((uint32_t)ml << 16);
    }
#pragma unroll
    for (int k = 26; k < 32; k++) w[k] = 0u;

    uint4* d4 = (uint4*)(dst + (size_t)idx * 64);
#pragma unroll
    for (int c = 0; c < 8; c++)
        d4[c] = make_uint4(w[4*c], w[4*c+1], w[4*c+2], w[4*c+3]);
}

__global__ void prep_kernel(const float* __restrict__ X,
                            const float* __restrict__ Y, int N, int M) {
    int b = blockIdx.x;
    if (b == 0 && threadIdx.x == 0) g_done = 0;
    if (b < 64) {
        int idx = b * 256 + threadIdx.x;
        if (idx < N) split_store(X, idx, g_A, true,  g_invx, g_rowmin);
    } else {
        int idx = (b - 64) * 256 + threadIdx.x;
        if (idx < M) split_store(Y, idx, g_B, false, g_invy, g_colmin);
    }
}

// ---------------------------------------------------------------- pair kernel
__global__ void __launch_bounds__(256, 2) pair_mma_kernel() {
    extern __shared__ __align__(16) char smem[];
    const uint32_t sb = smem_u32(smem);

    const int tid  = threadIdx.x;
    const int wid  = tid >> 5;
    const int lane = tid & 31;
    const int i0   = blockIdx.y * 128;
    const int jc0  = blockIdx.x * 1024;          // chunk base column

    const int wr = wid & 3;
    const int wc = wid >> 2;
    const int lr = lane & 15;
    const int lc = lane >> 4;
    const float INF = __int_as_float(0x7f800000);

    const int cr = tid >> 3, cc = tid & 7;       // 16B-chunk coords (4/thread)
    const uint32_t swz0 = SMEM_SWZ(cr * 128 + cc * 16);
    const uint32_t swz1 = SMEM_SWZ((cr + 32) * 128 + cc * 16);
    const uint32_t swz2 = SMEM_SWZ((cr + 64) * 128 + cc * 16);
    const uint32_t swz3 = SMEM_SWZ((cr + 96) * 128 + cc * 16);
    const size_t   goff = (size_t)cr * 128 + cc * 16;

    // ---- prologue: async-copy A tile + B tile 0
    {
        const char* Ag = (const char*)g_A + (size_t)i0 * 128;
        CPASYNC16(sb + SM_A + swz0, Ag + goff);
        CPASYNC16(sb + SM_A + swz1, Ag + goff + 32 * 128);
        CPASYNC16(sb + SM_A + swz2, Ag + goff + 64 * 128);
        CPASYNC16(sb + SM_A + swz3, Ag + goff + 96 * 128);
        const char* Bg = (const char*)g_B + (size_t)jc0 * 128;
        CPASYNC16(sb + SM_B + swz0, Bg + goff);
        CPASYNC16(sb + SM_B + swz1, Bg + goff + 32 * 128);
        CPASYNC16(sb + SM_B + swz2, Bg + goff + 64 * 128);
        CPASYNC16(sb + SM_B + swz3, Bg + goff + 96 * 128);
        CPCOMMIT();
        float4 w = ((const float4*)(g_invy + jc0))[tid];
        ((float4*)(smem + SM_NY))[tid] =
            make_float4(-2.f*w.x, -2.f*w.y, -2.f*w.z, -2.f*w.w);
    }

    float nxv[4];
#pragma unroll
    for (int mt = 0; mt < 2; mt++)
#pragma unroll
        for (int rr = 0; rr < 2; rr++)
            nxv[2*mt+rr] = -2.0f * g_invx[i0 + 32*wr + 16*mt + 8*rr + (lane >> 2)];

    CPWAIT0();
    __syncthreads();

    // ---- A fragments once per sweep
    uint32_t afr[4][2][4];
#pragma unroll
    for (int ks = 0; ks < 4; ks++)
#pragma unroll
        for (int mt = 0; mt < 2; mt++) {
            int row = 32*wr + 16*mt + lr;
            LDSM4(afr[ks][mt], sb + SM_A + SMEM_SWZ(row*128 + ks*32 + lc*16));
        }

    // prefetch B tile 1
    {
        const char* Bg = (const char*)g_B + (size_t)(jc0 + 128) * 128;
        uint32_t d = sb + SM_B + 16384;
        CPASYNC16(d + swz0, Bg + goff);
        CPASYNC16(d + swz1, Bg + goff + 32 * 128);
        CPASYNC16(d + swz2, Bg + goff + 64 * 128);
        CPASYNC16(d + swz3, Bg + goff + 96 * 128);
        CPCOMMIT();
    }

    const float* sNY = (const float*)(smem + SM_NY);
    float rmin[4] = {INF, INF, INF, INF};

    const int b16 = (lane >> 4) & 1;
    const int b8  = (lane >> 3) & 1;
    const int b4  = (lane >> 2) & 1;
    const int ownCol = 8 * (2 * b16 + b8) + 2 * (lane & 3) + b4;

#pragma unroll 1
    for (int t = 0; t < TILES_PER_SWEEP; t++) {
        if (t > 0) {
            CPWAIT0();
            __syncthreads();
            if (t + 1 < TILES_PER_SWEEP) {
                const char* Bg =
                    (const char*)g_B + (size_t)(jc0 + (t + 1) * 128) * 128;
                uint32_t d = sb + SM_B + ((t + 1) & 1) * 16384;
                CPASYNC16(d + swz0, Bg + goff);
                CPASYNC16(d + swz1, Bg + goff + 32 * 128);
                CPASYNC16(d + swz2, Bg + goff + 64 * 128);
                CPASYNC16(d + swz3, Bg + goff + 96 * 128);
                CPCOMMIT();
            }
        }

        const uint32_t sBb = sb + SM_B + (t & 1) * 16384;
        const int jt = t * 128;

#pragma unroll
        for (int h = 0; h < 2; h++) {
            // nyv loads first (independent LDS, overlaps fragment loads)
            float nyv[8];
#pragma unroll
            for (int nt = 0; nt < 4; nt++)
#pragma unroll
                for (int c = 0; c < 2; c++)
                    nyv[2*nt+c] = sNY[jt + 64*wc + 32*h + 8*nt + 2*(lane & 3) + c];

            // one-deep pipelined B fragments: load ks+1 before MMAs of ks
            uint32_t b[2][2][4];
            {
                int row0 = 64*wc + 32*h + lr;
                LDSM4(b[0][0], sBb + SMEM_SWZ(row0*128 + lc*16));
                LDSM4(b[0][1], sBb + SMEM_SWZ((row0+16)*128 + lc*16));
            }

            float acc[2][4][4];
#pragma unroll
            for (int mt = 0; mt < 2; mt++)
#pragma unroll
                for (int nt = 0; nt < 4; nt++)
#pragma unroll
                    for (int e = 0; e < 4; e++) acc[mt][nt][e] = 0.0f;

#pragma unroll
            for (int ks = 0; ks < 4; ks++) {
                if (ks < 3) {
                    int row = 64*wc + 32*h + lr;
                    uint32_t off = (ks+1)*32 + lc*16;
                    LDSM4(b[(ks+1)&1][0], sBb + SMEM_SWZ(row*128 + off));
                    LDSM4(b[(ks+1)&1][1], sBb + SMEM_SWZ((row+16)*128 + off));
                }
#pragma unroll
                for (int mt = 0; mt < 2; mt++)
#pragma unroll
                    for (int nt = 0; nt < 4; nt++) {
                        int np = nt >> 1, od = nt & 1;
                        MMA16816(acc[mt][nt], afr[ks][mt],
                                 b[ks&1][np][od], b[ks&1][np][od+2]);
                    }
            }

            // epilogue: 2 MUL + 2 MIN per pair
            float v[8];
#pragma unroll
            for (int k = 0; k < 8; k++) v[k] = INF;
#pragma unroll
            for (int mt = 0; mt < 2; mt++)
#pragma unroll
                for (int nt = 0; nt < 4; nt++) {
                    float* c = acc[mt][nt];
                    rmin[2*mt]   = fminf(rmin[2*mt],
                                   fminf(c[0]*nyv[2*nt], c[1]*nyv[2*nt+1]));
                    rmin[2*mt+1] = fminf(rmin[2*mt+1],
                                   fminf(c[2]*nyv[2*nt], c[3]*nyv[2*nt+1]));
                    v[2*nt]   = fminf(v[2*nt],
                                fminf(c[0]*nxv[2*mt], c[2]*nxv[2*mt+1]));
                    v[2*nt+1] = fminf(v[2*nt+1],
                                fminf(c[1]*nxv[2*mt], c[3]*nxv[2*mt+1]));
                }

            // ---- reduce-scatter col mins across the 8 duplicate lanes
#pragma unroll
            for (int q = 0; q < 4; q++) {
                float x = b16 ? v[q] : v[q + 4];
                float r = __shfl_xor_sync(0xffffffffu, x, 16);
                if (b16) v[q + 4] = fminf(v[q + 4], r);
                else     v[q]     = fminf(v[q], r);
            }
#pragma unroll
            for (int g = 0; g < 8; g += 4)
#pragma unroll
                for (int q = 0; q < 2; q++) {
                    float x = b8 ? v[g + q] : v[g + q + 2];
                    float r = __shfl_xor_sync(0xffffffffu, x, 8);
                    if (b8) v[g + q + 2] = fminf(v[g + q + 2], r);
                    else    v[g + q]     = fminf(v[g + q], r);
                }
#pragma unroll
            for (int g = 0; g < 8; g += 2) {
                float x = b4 ? v[g] : v[g + 1];
                float r = __shfl_xor_sync(0xffffffffu, x, 4);
                if (b4) v[g + 1] = fminf(v[g + 1], r);
                else    v[g]     = fminf(v[g], r);
            }
            float owned = b16 ? (b8 ? (b4 ? v[7] : v[6]) : (b4 ? v[5] : v[4]))
                              : (b8 ? (b4 ? v[3] : v[2]) : (b4 ? v[1] : v[0]));
            atomicMin(&g_colmin[jc0 + jt + 64*wc + 32*h + ownCol],
                      __float_as_int(fmaxf(owned, 0.0f)));
        }
    }

    // ---- sweep epilogue: row mins
    float* rowp = (float*)(smem + SM_ROW);       // [2][128]
#pragma unroll
    for (int k = 0; k < 4; k++) {
        float v = rmin[k];
        v = fminf(v, __shfl_xor_sync(0xffffffffu, v, 1));
        v = fminf(v, __shfl_xor_sync(0xffffffffu, v, 2));
        if ((lane & 3) == 0)
            rowp[wc*128 + 32*wr + 16*(k >> 1) + 8*(k & 1) + (lane >> 2)] = v;
    }
    __syncthreads();
    if (tid < 128) {
        float rv = fminf(rowp[tid], rowp[128 + tid]);
        atomicMin(&g_rowmin[i0 + tid], __float_as_int(fmaxf(rv, 0.0f)));
    }
}

// ---------------------------------------------------------------- finalize
__global__ void finalize_kernel(int N, int M, float* out) {
    __shared__ float red[256];
    __shared__ int   lastFlag;
    int  b     = blockIdx.x;
    bool isRow = (b < 64);
    int  idx   = (isRow ? b : b - 64) * 256 + threadIdx.x;
    float val  = 0.0f;
    int   lim  = isRow ? N : M;
    if (idx < lim) {
        float m   = fmaxf(__int_as_float(isRow ? g_rowmin[idx] : g_colmin[idx]),
                          0.0f);
        float inv = isRow ? g_invx[idx] : g_invy[idx];
        float u   = fmaf(2.0f * m, inv, 1.0f);
        val       = logf(u + sqrtf(fmaxf(u * u - 1.0f, 0.0f)));
    }
    red[threadIdx.x] = val;
    __syncthreads();
    for (int s = 128; s > 0; s >>= 1) {
        if (threadIdx.x < s) red[threadIdx.x] += red[threadIdx.x + s];
        __syncthreads();
    }
    if (threadIdx.x == 0) {
        g_part[b] = red[0] * (isRow ? 1.0f / (float)N : 1.0f / (float)M);
        __threadfence();
        int t = atomicAdd(&g_done, 1);
        lastFlag = (t == 127);
    }
    __syncthreads();
    if (lastFlag) {
        red[threadIdx.x] = (threadIdx.x < 128) ? g_part[threadIdx.x] : 0.0f;
        __syncthreads();
        for (int s = 128; s > 0; s >>= 1) {
            if (threadIdx.x < s) red[threadIdx.x] += red[threadIdx.x + s];
            __syncthreads();
        }
        if (threadIdx.x == 0) out[0] = red[0];
    }
}

// ---------------------------------------------------------------- launch
extern "C" void kernel_launch(void* const* d_in, const int* in_sizes, int n_in,
                              void* d_out, int out_size) {
    const float* X = (const float*)d_in[0];
    const float* Y = (const float*)d_in[1];
    int N = in_sizes[0] / 16;
    int M = in_sizes[1] / 16;

    static int configured = 0;
    if (!configured) {
        cudaFuncSetAttribute(pair_mma_kernel,
                             cudaFuncAttributeMaxDynamicSharedMemorySize,
                             SM_TOT);
        configured = 1;
    }

    prep_kernel<<<128, 256>>>(X, Y, N, M);

    dim3 grid(M / 1024, N / 128);
    pair_mma_kernel<<<grid, 256, SM_TOT>>>();

    finalize_kernel<<<128, 256>>>(N, M, (float*)d_out);
}

// round 10
// speedup vs baseline: 1.1248x; 1.0129x over previous
#include <cuda_runtime.h>
#include <cuda_bf16.h>
#include <cstdint>

// ============================================================================
// Hyperbolic averaged Hausdorff loss via tensor-core mma.sync (bf16).
// (build targets plain sm_103: tcgen05 unavailable; legacy HMMA path)
//
// K=64 norm-fold GEMM: acc_ij = dot_ij - (xn_i + yn_j)/2 (bf16 hi/lo split).
// Row-min of acc*(-2invy_j), col-min of acc*(-2invx_i); arcosh at the end.
//
// R10 = R7 + warp phase desync (h order xor'd with warp-row parity so warps
// sharing an SMSP alternate tensor-burst and MIO-burst phases) + prep kernel
// spread over 256 blocks.
// ============================================================================

#define NPTS 16384
#define TILES_PER_SWEEP 8

__device__ float g_invx[NPTS], g_invy[NPTS];
__device__ int   g_rowmin[NPTS], g_colmin[NPTS];
__device__ float g_part[128];
__device__ int   g_done;
__device__ __nv_bfloat16 g_A[NPTS * 64];
__device__ __nv_bfloat16 g_B[NPTS * 64];

__device__ __forceinline__ uint32_t smem_u32(const void* p) {
    uint32_t a;
    asm("{ .reg .u64 t; cvta.to.shared.u64 t, %1; cvt.u32.u64 %0, t; }"
        : "=r"(a) : "l"(p));
    return a;
}
#define SMEM_SWZ(o) ((o) ^ ((((o) >> 3) & 0x70)))

#define CPASYNC16(dst, src) \
    asm volatile("cp.async.cg.shared.global [%0], [%1], 16;" \
                 :: "r"(dst), "l"(src))
#define CPCOMMIT() asm volatile("cp.async.commit_group;")
#define CPWAIT0()  asm volatile("cp.async.wait_group 0;")

#define LDSM4(r, addr)                                                      \
    asm volatile("ldmatrix.sync.aligned.m8n8.x4.shared.b16 "                \
                 "{%0,%1,%2,%3}, [%4];"                                     \
                 : "=r"((r)[0]), "=r"((r)[1]), "=r"((r)[2]), "=r"((r)[3])   \
                 : "r"(addr))

#define MMA16816(d, a, b0, b1)                                              \
    asm volatile("mma.sync.aligned.m16n8k16.row.col.f32.bf16.bf16.f32 "     \
                 "{%0,%1,%2,%3}, {%4,%5,%6,%7}, {%8,%9}, {%0,%1,%2,%3};"    \
                 : "+f"((d)[0]), "+f"((d)[1]), "+f"((d)[2]), "+f"((d)[3])   \
                 : "r"((a)[0]), "r"((a)[1]), "r"((a)[2]), "r"((a)[3]),      \
                   "r"(b0), "r"(b1))

// ---------------------------------------------------------------- smem layout
#define SM_A    0                       // 16384   (128 rows x 128B)
#define SM_B    16384                   // 2 x 16384 -> ends 49152
#define SM_NY   49152                   // 1024 x f32 = 4096 (-2*invy of chunk)
#define SM_ROW  53248                   // 2 x 128 x f32 = 1024
#define SM_TOT  54272

// ---------------------------------------------------------------- prep kernel
union BU { __nv_bfloat16 b; unsigned short u; };
__device__ __forceinline__ unsigned short bfu(float x) {
    BU t; t.b = __float2bfloat16(x); return t.u;
}
__device__ __forceinline__ float bff(unsigned short u) {
    BU t; t.u = u; return __bfloat162float(t.b);
}

__device__ __forceinline__ void split_store(const float* src, int idx,
                                            __nv_bfloat16* dst, bool isA,
                                            float* inv, int* mn) {
    float v[16];
    const float4* p = (const float4*)(src + (size_t)idx * 16);
    float4 q0 = p[0], q1 = p[1], q2 = p[2], q3 = p[3];
    v[0]=q0.x; v[1]=q0.y; v[2]=q0.z; v[3]=q0.w;
    v[4]=q1.x; v[5]=q1.y; v[6]=q1.z; v[7]=q1.w;
    v[8]=q2.x; v[9]=q2.y; v[10]=q2.z; v[11]=q2.w;
    v[12]=q3.x; v[13]=q3.y; v[14]=q3.z; v[15]=q3.w;
    float s = 0.f;
#pragma unroll
    for (int d = 0; d < 16; d++) s += v[d] * v[d];
    inv[idx] = 1.0f / (1.0f - s);
    mn[idx]  = 0x7f800000;

    unsigned short hi[16], lo[16];
#pragma unroll
    for (int d = 0; d < 16; d++) {
        hi[d] = bfu(v[d]);
        lo[d] = bfu(v[d] - bff(hi[d]));
    }
    uint32_t w[32];
#pragma unroll
    for (int k = 0; k < 8; k++) {
        uint32_t hp = (uint32_t)hi[2*k] | ((uint32_t)hi[2*k+1] << 16);
        uint32_t lp = (uint32_t)lo[2*k] | ((uint32_t)lo[2*k+1] << 16);
        w[k]      = hp;
        w[8 + k]  = isA ? lp : hp;
        w[16 + k] = isA ? hp : lp;
    }
    if (isA) {
        unsigned short nh = bfu(s);
        unsigned short nl = bfu(s - bff(nh));
        unsigned short one = bfu(1.0f);
        w[24] = (uint32_t)nh | ((uint32_t)nl << 16);
        w[25] = (uint32_t)one | ((uint32_t)one << 16);
    } else {
        float m = -0.5f * s;
        unsigned short mh = bfu(m);
        unsigned short ml = bfu(m - bff(mh));
        unsigned short nhalf = bfu(-0.5f);
        w[24] = (uint32_t)nhalf | ((uint32_t)nhalf << 16);
        w[25] = (uint32_t)mh | ((uint32_t)ml << 16);
    }
#pragma unroll
    for (int k = 26; k < 32; k++) w[k] = 0u;

    uint4* d4 = (uint4*)(dst + (size_t)idx * 64);
#pragma unroll
    for (int c = 0; c < 8; c++)
        d4[c] = make_uint4(w[4*c], w[4*c+1], w[4*c+2], w[4*c+3]);
}

// 256 blocks x 128 threads: blocks [0,128) X, [128,256) Y
__global__ void prep_kernel(const float* __restrict__ X,
                            const float* __restrict__ Y, int N, int M) {
    int b = blockIdx.x;
    if (b == 0 && threadIdx.x == 0) g_done = 0;
    if (b < 128) {
        int idx = b * 128 + threadIdx.x;
        if (idx < N) split_store(X, idx, g_A, true,  g_invx, g_rowmin);
    } else {
        int idx = (b - 128) * 128 + threadIdx.x;
        if (idx < M) split_store(Y, idx, g_B, false, g_invy, g_colmin);
    }
}

// ---------------------------------------------------------------- pair kernel
__global__ void __launch_bounds__(256, 2) pair_mma_kernel() {
    extern __shared__ __align__(16) char smem[];
    const uint32_t sb = smem_u32(smem);

    const int tid  = threadIdx.x;
    const int wid  = tid >> 5;
    const int lane = tid & 31;
    const int i0   = blockIdx.y * 128;
    const int jc0  = blockIdx.x * 1024;          // chunk base column

    const int wr = wid & 3;
    const int wc = wid >> 2;
    const int lr = lane & 15;
    const int lc = lane >> 4;
    const float INF = __int_as_float(0x7f800000);

    const int cr = tid >> 3, cc = tid & 7;       // 16B-chunk coords (4/thread)
    const uint32_t swz0 = SMEM_SWZ(cr * 128 + cc * 16);
    const uint32_t swz1 = SMEM_SWZ((cr + 32) * 128 + cc * 16);
    const uint32_t swz2 = SMEM_SWZ((cr + 64) * 128 + cc * 16);
    const uint32_t swz3 = SMEM_SWZ((cr + 96) * 128 + cc * 16);
    const size_t   goff = (size_t)cr * 128 + cc * 16;

    // ---- prologue: async-copy A tile + B tile 0
    {
        const char* Ag = (const char*)g_A + (size_t)i0 * 128;
        CPASYNC16(sb + SM_A + swz0, Ag + goff);
        CPASYNC16(sb + SM_A + swz1, Ag + goff + 32 * 128);
        CPASYNC16(sb + SM_A + swz2, Ag + goff + 64 * 128);
        CPASYNC16(sb + SM_A + swz3, Ag + goff + 96 * 128);
        const char* Bg = (const char*)g_B + (size_t)jc0 * 128;
        CPASYNC16(sb + SM_B + swz0, Bg + goff);
        CPASYNC16(sb + SM_B + swz1, Bg + goff + 32 * 128);
        CPASYNC16(sb + SM_B + swz2, Bg + goff + 64 * 128);
        CPASYNC16(sb + SM_B + swz3, Bg + goff + 96 * 128);
        CPCOMMIT();
        float4 w = ((const float4*)(g_invy + jc0))[tid];
        ((float4*)(smem + SM_NY))[tid] =
            make_float4(-2.f*w.x, -2.f*w.y, -2.f*w.z, -2.f*w.w);
    }

    float nxv[4];
#pragma unroll
    for (int mt = 0; mt < 2; mt++)
#pragma unroll
        for (int rr = 0; rr < 2; rr++)
            nxv[2*mt+rr] = -2.0f * g_invx[i0 + 32*wr + 16*mt + 8*rr + (lane >> 2)];

    CPWAIT0();
    __syncthreads();

    // ---- A fragments once per sweep
    uint32_t afr[4][2][4];
#pragma unroll
    for (int ks = 0; ks < 4; ks++)
#pragma unroll
        for (int mt = 0; mt < 2; mt++) {
            int row = 32*wr + 16*mt + lr;
            LDSM4(afr[ks][mt], sb + SM_A + SMEM_SWZ(row*128 + ks*32 + lc*16));
        }

    // prefetch B tile 1
    {
        const char* Bg = (const char*)g_B + (size_t)(jc0 + 128) * 128;
        uint32_t d = sb + SM_B + 16384;
        CPASYNC16(d + swz0, Bg + goff);
        CPASYNC16(d + swz1, Bg + goff + 32 * 128);
        CPASYNC16(d + swz2, Bg + goff + 64 * 128);
        CPASYNC16(d + swz3, Bg + goff + 96 * 128);
        CPCOMMIT();
    }

    const float* sNY = (const float*)(smem + SM_NY);
    float rmin[4] = {INF, INF, INF, INF};

    const int b16 = (lane >> 4) & 1;
    const int b8  = (lane >> 3) & 1;
    const int b4  = (lane >> 2) & 1;
    const int ownCol = 8 * (2 * b16 + b8) + 2 * (lane & 3) + b4;
    const int hswap = wr & 1;                    // warp phase desync

#pragma unroll 1
    for (int t = 0; t < TILES_PER_SWEEP; t++) {
        if (t > 0) {
            CPWAIT0();
            __syncthreads();
            if (t + 1 < TILES_PER_SWEEP) {
                const char* Bg =
                    (const char*)g_B + (size_t)(jc0 + (t + 1) * 128) * 128;
                uint32_t d = sb + SM_B + ((t + 1) & 1) * 16384;
                CPASYNC16(d + swz0, Bg + goff);
                CPASYNC16(d + swz1, Bg + goff + 32 * 128);
                CPASYNC16(d + swz2, Bg + goff + 64 * 128);
                CPASYNC16(d + swz3, Bg + goff + 96 * 128);
                CPCOMMIT();
            }
        }

        const uint32_t sBb = sb + SM_B + (t & 1) * 16384;
        const int jt = t * 128;

#pragma unroll
        for (int hh = 0; hh < 2; hh++) {
            const int h = hh ^ hswap;            // desync: odd warp-rows run
                                                 // h=1 first, evens h=0 first
            float nyv[8];
#pragma unroll
            for (int nt = 0; nt < 4; nt++)
#pragma unroll
                for (int c = 0; c < 2; c++)
                    nyv[2*nt+c] = sNY[jt + 64*wc + 32*h + 8*nt + 2*(lane & 3) + c];

            float acc[2][4][4];
#pragma unroll
            for (int mt = 0; mt < 2; mt++)
#pragma unroll
                for (int nt = 0; nt < 4; nt++)
#pragma unroll
                    for (int e = 0; e < 4; e++) acc[mt][nt][e] = 0.0f;

#pragma unroll
            for (int ks = 0; ks < 4; ks++) {
                uint32_t b[2][4];
#pragma unroll
                for (int np = 0; np < 2; np++) {
                    int row = 64*wc + 32*h + 16*np + lr;
                    LDSM4(b[np], sBb + SMEM_SWZ(row*128 + ks*32 + lc*16));
                }
#pragma unroll
                for (int mt = 0; mt < 2; mt++)
#pragma unroll
                    for (int nt = 0; nt < 4; nt++) {
                        int np = nt >> 1, od = nt & 1;
                        MMA16816(acc[mt][nt], afr[ks][mt], b[np][od], b[np][od+2]);
                    }
            }

            // epilogue: 2 MUL + 2 MIN per pair
            float v[8];
#pragma unroll
            for (int k = 0; k < 8; k++) v[k] = INF;
#pragma unroll
            for (int mt = 0; mt < 2; mt++)
#pragma unroll
                for (int nt = 0; nt < 4; nt++) {
                    float* c = acc[mt][nt];
                    rmin[2*mt]   = fminf(rmin[2*mt],
                                   fminf(c[0]*nyv[2*nt], c[1]*nyv[2*nt+1]));
                    rmin[2*mt+1] = fminf(rmin[2*mt+1],
                                   fminf(c[2]*nyv[2*nt], c[3]*nyv[2*nt+1]));
                    v[2*nt]   = fminf(v[2*nt],
                                fminf(c[0]*nxv[2*mt], c[2]*nxv[2*mt+1]));
                    v[2*nt+1] = fminf(v[2*nt+1],
                                fminf(c[1]*nxv[2*mt], c[3]*nxv[2*mt+1]));
                }

            // ---- reduce-scatter col mins across the 8 duplicate lanes
#pragma unroll
            for (int q = 0; q < 4; q++) {
                float x = b16 ? v[q] : v[q + 4];
                float r = __shfl_xor_sync(0xffffffffu, x, 16);
                if (b16) v[q + 4] = fminf(v[q + 4], r);
                else     v[q]     = fminf(v[q], r);
            }
#pragma unroll
            for (int g = 0; g < 8; g += 4)
#pragma unroll
                for (int q = 0; q < 2; q++) {
                    float x = b8 ? v[g + q] : v[g + q + 2];
                    float r = __shfl_xor_sync(0xffffffffu, x, 8);
                    if (b8) v[g + q + 2] = fminf(v[g + q + 2], r);
                    else    v[g + q]     = fminf(v[g + q], r);
                }
#pragma unroll
            for (int g = 0; g < 8; g += 2) {
                float x = b4 ? v[g] : v[g + 1];
                float r = __shfl_xor_sync(0xffffffffu, x, 4);
                if (b4) v[g + 1] = fminf(v[g + 1], r);
                else    v[g]     = fminf(v[g], r);
            }
            float owned = b16 ? (b8 ? (b4 ? v[7] : v[6]) : (b4 ? v[5] : v[4]))
                              : (b8 ? (b4 ? v[3] : v[2]) : (b4 ? v[1] : v[0]));
            atomicMin(&g_colmin[jc0 + jt + 64*wc + 32*h + ownCol],
                      __float_as_int(fmaxf(owned, 0.0f)));
        }
    }

    // ---- sweep epilogue: row mins
    float* rowp = (float*)(smem + SM_ROW);       // [2][128]
#pragma unroll
    for (int k = 0; k < 4; k++) {
        float v = rmin[k];
        v = fminf(v, __shfl_xor_sync(0xffffffffu, v, 1));
        v = fminf(v, __shfl_xor_sync(0xffffffffu, v, 2));
        if ((lane & 3) == 0)
            rowp[wc*128 + 32*wr + 16*(k >> 1) + 8*(k & 1) + (lane >> 2)] = v;
    }
    __syncthreads();
    if (tid < 128) {
        float rv = fminf(rowp[tid], rowp[128 + tid]);
        atomicMin(&g_rowmin[i0 + tid], __float_as_int(fmaxf(rv, 0.0f)));
    }
}

// ---------------------------------------------------------------- finalize
__global__ void finalize_kernel(int N, int M, float* out) {
    __shared__ float red[256];
    __shared__ int   lastFlag;
    int  b     = blockIdx.x;
    bool isRow = (b < 64);
    int  idx   = (isRow ? b : b - 64) * 256 + threadIdx.x;
    float val  = 0.0f;
    int   lim  = isRow ? N : M;
    if (idx < lim) {
        float m   = fmaxf(__int_as_float(isRow ? g_rowmin[idx] : g_colmin[idx]),
                          0.0f);
        float inv = isRow ? g_invx[idx] : g_invy[idx];
        float u   = fmaf(2.0f * m, inv, 1.0f);
        val       = logf(u + sqrtf(fmaxf(u * u - 1.0f, 0.0f)));
    }
    red[threadIdx.x] = val;
    __syncthreads();
    for (int s = 128; s > 0; s >>= 1) {
        if (threadIdx.x < s) red[threadIdx.x] += red[threadIdx.x + s];
        __syncthreads();
    }
    if (threadIdx.x == 0) {
        g_part[b] = red[0] * (isRow ? 1.0f / (float)N : 1.0f / (float)M);
        __threadfence();
        int t = atomicAdd(&g_done, 1);
        lastFlag = (t == 127);
    }
    __syncthreads();
    if (lastFlag) {
        red[threadIdx.x] = (threadIdx.x < 128) ? g_part[threadIdx.x] : 0.0f;
        __syncthreads();
        for (int s = 128; s > 0; s >>= 1) {
            if (threadIdx.x < s) red[threadIdx.x] += red[threadIdx.x + s];
            __syncthreads();
        }
        if (threadIdx.x == 0) out[0] = red[0];
    }
}

// ---------------------------------------------------------------- launch
extern "C" void kernel_launch(void* const* d_in, const int* in_sizes, int n_in,
                              void* d_out, int out_size) {
    const float* X = (const float*)d_in[0];
    const float* Y = (const float*)d_in[1];
    int N = in_sizes[0] / 16;
    int M = in_sizes[1] / 16;

    static int configured = 0;
    if (!configured) {
        cudaFuncSetAttribute(pair_mma_kernel,
                             cudaFuncAttributeMaxDynamicSharedMemorySize,
                             SM_TOT);
        configured = 1;
    }

    prep_kernel<<<256, 128>>>(X, Y, N, M);

    dim3 grid(M / 1024, N / 128);
    pair_mma_kernel<<<grid, 256, SM_TOT>>>();

    finalize_kernel<<<128, 256>>>(N, M, (float*)d_out);
}

// round 11
// speedup vs baseline: 1.2597x; 1.1199x over previous
#include <cuda_runtime.h>
#include <cuda_bf16.h>
#include <cstdint>

// ============================================================================
// Hyperbolic averaged Hausdorff loss via tensor-core mma.sync (bf16).
// (build targets plain sm_103: tcgen05 unavailable; legacy HMMA path)
//
// R11: invy folded into B at prep time.
//   B'_j = B_j * invy_j (data cols y'=y*invy, hi/lo split after scaling;
//   norm-fold cols: c=-invy/2 and m'=-yn*invy/2, each hi/lo split)
//   A norm cols: [xn_h, xn_h, xn_l, 1, 1]
//   => acc_ij = (dot - (xn+yn)/2)*invy_j = -sqdist*invy_j/2
//   row: m_row = min_j sqdist*invy/2 = -max_j acc      (1 MAX/elem)
//   col: m_col = min_i sqdist*invx*invy/2 = -max_i(acc*invx)  (MUL+MAX/elem)
//   finalize: u_row = 1 + 4*invx*m_row ; u_col = 1 + 4*m_col ; arcosh.
// Persistent-A sweep, cp.async double buffer, 1 barrier/tile, reduce-scatter
// col reduction with direct lane atomics (all from R7 baseline).
// ============================================================================

#define NPTS 16384
#define TILES_PER_SWEEP 8

__device__ float g_invx[NPTS];
__device__ int   g_rowmin[NPTS], g_colmin[NPTS];
__device__ float g_part[128];
__device__ int   g_done;
__device__ __nv_bfloat16 g_A[NPTS * 64];
__device__ __nv_bfloat16 g_B[NPTS * 64];

__device__ __forceinline__ uint32_t smem_u32(const void* p) {
    uint32_t a;
    asm("{ .reg .u64 t; cvta.to.shared.u64 t, %1; cvt.u32.u64 %0, t; }"
        : "=r"(a) : "l"(p));
    return a;
}
#define SMEM_SWZ(o) ((o) ^ ((((o) >> 3) & 0x70)))

#define CPASYNC16(dst, src) \
    asm volatile("cp.async.cg.shared.global [%0], [%1], 16;" \
                 :: "r"(dst), "l"(src))
#define CPCOMMIT() asm volatile("cp.async.commit_group;")
#define CPWAIT0()  asm volatile("cp.async.wait_group 0;")

#define LDSM4(r, addr)                                                      \
    asm volatile("ldmatrix.sync.aligned.m8n8.x4.shared.b16 "                \
                 "{%0,%1,%2,%3}, [%4];"                                     \
                 : "=r"((r)[0]), "=r"((r)[1]), "=r"((r)[2]), "=r"((r)[3])   \
                 : "r"(addr))

#define MMA16816(d, a, b0, b1)                                              \
    asm volatile("mma.sync.aligned.m16n8k16.row.col.f32.bf16.bf16.f32 "     \
                 "{%0,%1,%2,%3}, {%4,%5,%6,%7}, {%8,%9}, {%0,%1,%2,%3};"    \
                 : "+f"((d)[0]), "+f"((d)[1]), "+f"((d)[2]), "+f"((d)[3])   \
                 : "r"((a)[0]), "r"((a)[1]), "r"((a)[2]), "r"((a)[3]),      \
                   "r"(b0), "r"(b1))

// ---------------------------------------------------------------- smem layout
#define SM_A    0                       // 16384   (128 rows x 128B)
#define SM_B    16384                   // 2 x 16384 -> ends 49152
#define SM_ROW  49152                   // 2 x 128 x f32 = 1024
#define SM_TOT  50176

// ---------------------------------------------------------------- prep kernel
union BU { __nv_bfloat16 b; unsigned short u; };
__device__ __forceinline__ unsigned short bfu(float x) {
    BU t; t.b = __float2bfloat16(x); return t.u;
}
__device__ __forceinline__ float bff(unsigned short u) {
    BU t; t.u = u; return __bfloat162float(t.b);
}

__device__ __forceinline__ void split_store(const float* src, int idx,
                                            __nv_bfloat16* dst, bool isA,
                                            int* mn) {
    float v[16];
    const float4* p = (const float4*)(src + (size_t)idx * 16);
    float4 q0 = p[0], q1 = p[1], q2 = p[2], q3 = p[3];
    v[0]=q0.x; v[1]=q0.y; v[2]=q0.z; v[3]=q0.w;
    v[4]=q1.x; v[5]=q1.y; v[6]=q1.z; v[7]=q1.w;
    v[8]=q2.x; v[9]=q2.y; v[10]=q2.z; v[11]=q2.w;
    v[12]=q3.x; v[13]=q3.y; v[14]=q3.z; v[15]=q3.w;
    float s = 0.f;
#pragma unroll
    for (int d = 0; d < 16; d++) s += v[d] * v[d];
    float inv = 1.0f / (1.0f - s);
    if (isA) g_invx[idx] = inv;
    mn[idx] = 0x7f800000;

    // B rows are pre-scaled by invy
    if (!isA) {
#pragma unroll
        for (int d = 0; d < 16; d++) v[d] *= inv;
    }

    unsigned short hi[16], lo[16];
#pragma unroll
    for (int d = 0; d < 16; d++) {
        hi[d] = bfu(v[d]);
        lo[d] = bfu(v[d] - bff(hi[d]));
    }
    uint32_t w[32];
#pragma unroll
    for (int k = 0; k < 8; k++) {
        uint32_t hp = (uint32_t)hi[2*k] | ((uint32_t)hi[2*k+1] << 16);
        uint32_t lp = (uint32_t)lo[2*k] | ((uint32_t)lo[2*k+1] << 16);
        w[k]      = hp;
        w[8 + k]  = isA ? lp : hp;
        w[16 + k] = isA ? hp : lp;
    }
    // norm-fold columns 48..52:
    //  A: [xn_h, xn_h, xn_l, 1, 1]
    //  B: [c_h,  c_l,  c_h,  m_h, m_l]   c = -invy/2, m = -yn*invy/2
    if (isA) {
        unsigned short nh = bfu(s);
        unsigned short nl = bfu(s - bff(nh));
        unsigned short one = bfu(1.0f);
        w[24] = (uint32_t)nh | ((uint32_t)nh << 16);
        w[25] = (uint32_t)nl | ((uint32_t)one << 16);
        w[26] = (uint32_t)one;
    } else {
        float c = -0.5f * inv;
        unsigned short ch = bfu(c);
        unsigned short cl = bfu(c - bff(ch));
        float m = -0.5f * s * inv;
        unsigned short mh = bfu(m);
        unsigned short ml = bfu(m - bff(mh));
        w[24] = (uint32_t)ch | ((uint32_t)cl << 16);
        w[25] = (uint32_t)ch | ((uint32_t)mh << 16);
        w[26] = (uint32_t)ml;
    }
#pragma unroll
    for (int k = 27; k < 32; k++) w[k] = 0u;

    uint4* d4 = (uint4*)(dst + (size_t)idx * 64);
#pragma unroll
    for (int c = 0; c < 8; c++)
        d4[c] = make_uint4(w[4*c], w[4*c+1], w[4*c+2], w[4*c+3]);
}

// 256 blocks x 128 threads: blocks [0,128) X, [128,256) Y
__global__ void prep_kernel(const float* __restrict__ X,
                            const float* __restrict__ Y, int N, int M) {
    int b = blockIdx.x;
    if (b == 0 && threadIdx.x == 0) g_done = 0;
    if (b < 128) {
        int idx = b * 128 + threadIdx.x;
        if (idx < N) split_store(X, idx, g_A, true,  g_rowmin);
    } else {
        int idx = (b - 128) * 128 + threadIdx.x;
        if (idx < M) split_store(Y, idx, g_B, false, g_colmin);
    }
}

// ---------------------------------------------------------------- pair kernel
__global__ void __launch_bounds__(256, 2) pair_mma_kernel() {
    extern __shared__ __align__(16) char smem[];
    const uint32_t sb = smem_u32(smem);

    const int tid  = threadIdx.x;
    const int wid  = tid >> 5;
    const int lane = tid & 31;
    const int i0   = blockIdx.y * 128;
    const int jc0  = blockIdx.x * 1024;          // chunk base column

    const int wr = wid & 3;
    const int wc = wid >> 2;
    const int lr = lane & 15;
    const int lc = lane >> 4;
    const float NINF = __int_as_float(0xff800000);

    const int cr = tid >> 3, cc = tid & 7;       // 16B-chunk coords (4/thread)
    const uint32_t swz0 = SMEM_SWZ(cr * 128 + cc * 16);
    const uint32_t swz1 = SMEM_SWZ((cr + 32) * 128 + cc * 16);
    const uint32_t swz2 = SMEM_SWZ((cr + 64) * 128 + cc * 16);
    const uint32_t swz3 = SMEM_SWZ((cr + 96) * 128 + cc * 16);
    const size_t   goff = (size_t)cr * 128 + cc * 16;

    // ---- prologue: async-copy A tile + B tile 0
    {
        const char* Ag = (const char*)g_A + (size_t)i0 * 128;
        CPASYNC16(sb + SM_A + swz0, Ag + goff);
        CPASYNC16(sb + SM_A + swz1, Ag + goff + 32 * 128);
        CPASYNC16(sb + SM_A + swz2, Ag + goff + 64 * 128);
        CPASYNC16(sb + SM_A + swz3, Ag + goff + 96 * 128);
        const char* Bg = (const char*)g_B + (size_t)jc0 * 128;
        CPASYNC16(sb + SM_B + swz0, Bg + goff);
        CPASYNC16(sb + SM_B + swz1, Bg + goff + 32 * 128);
        CPASYNC16(sb + SM_B + swz2, Bg + goff + 64 * 128);
        CPASYNC16(sb + SM_B + swz3, Bg + goff + 96 * 128);
        CPCOMMIT();
    }

    // per-row invx (positive, unscaled)
    float pxv[4];
#pragma unroll
    for (int mt = 0; mt < 2; mt++)
#pragma unroll
        for (int rr = 0; rr < 2; rr++)
            pxv[2*mt+rr] = g_invx[i0 + 32*wr + 16*mt + 8*rr + (lane >> 2)];

    CPWAIT0();
    __syncthreads();

    // ---- A fragments once per sweep
    uint32_t afr[4][2][4];
#pragma unroll
    for (int ks = 0; ks < 4; ks++)
#pragma unroll
        for (int mt = 0; mt < 2; mt++) {
            int row = 32*wr + 16*mt + lr;
            LDSM4(afr[ks][mt], sb + SM_A + SMEM_SWZ(row*128 + ks*32 + lc*16));
        }

    // prefetch B tile 1
    {
        const char* Bg = (const char*)g_B + (size_t)(jc0 + 128) * 128;
        uint32_t d = sb + SM_B + 16384;
        CPASYNC16(d + swz0, Bg + goff);
        CPASYNC16(d + swz1, Bg + goff + 32 * 128);
        CPASYNC16(d + swz2, Bg + goff + 64 * 128);
        CPASYNC16(d + swz3, Bg + goff + 96 * 128);
        CPCOMMIT();
    }

    float rmax[4] = {NINF, NINF, NINF, NINF};

    const int b16 = (lane >> 4) & 1;
    const int b8  = (lane >> 3) & 1;
    const int b4  = (lane >> 2) & 1;
    const int ownCol = 8 * (2 * b16 + b8) + 2 * (lane & 3) + b4;

#pragma unroll 1
    for (int t = 0; t < TILES_PER_SWEEP; t++) {
        if (t > 0) {
            CPWAIT0();
            __syncthreads();
            if (t + 1 < TILES_PER_SWEEP) {
                const char* Bg =
                    (const char*)g_B + (size_t)(jc0 + (t + 1) * 128) * 128;
                uint32_t d = sb + SM_B + ((t + 1) & 1) * 16384;
                CPASYNC16(d + swz0, Bg + goff);
                CPASYNC16(d + swz1, Bg + goff + 32 * 128);
                CPASYNC16(d + swz2, Bg + goff + 64 * 128);
                CPASYNC16(d + swz3, Bg + goff + 96 * 128);
                CPCOMMIT();
            }
        }

        const uint32_t sBb = sb + SM_B + (t & 1) * 16384;
        const int jt = t * 128;

#pragma unroll
        for (int h = 0; h < 2; h++) {
            float acc[2][4][4];
#pragma unroll
            for (int mt = 0; mt < 2; mt++)
#pragma unroll
                for (int nt = 0; nt < 4; nt++)
#pragma unroll
                    for (int e = 0; e < 4; e++) acc[mt][nt][e] = 0.0f;

#pragma unroll
            for (int ks = 0; ks < 4; ks++) {
                uint32_t b[2][4];
#pragma unroll
                for (int np = 0; np < 2; np++) {
                    int row = 64*wc + 32*h + 16*np + lr;
                    LDSM4(b[np], sBb + SMEM_SWZ(row*128 + ks*32 + lc*16));
                }
#pragma unroll
                for (int mt = 0; mt < 2; mt++)
#pragma unroll
                    for (int nt = 0; nt < 4; nt++) {
                        int np = nt >> 1, od = nt & 1;
                        MMA16816(acc[mt][nt], afr[ks][mt], b[np][od], b[np][od+2]);
                    }
            }

            // ---- epilogue: rows 1 MAX/elem (no mul); cols MUL+MAX/elem
            float v[8];
#pragma unroll
            for (int k = 0; k < 8; k++) v[k] = NINF;
#pragma unroll
            for (int mt = 0; mt < 2; mt++)
#pragma unroll
                for (int nt = 0; nt < 4; nt++) {
                    float* c = acc[mt][nt];
                    rmax[2*mt]   = fmaxf(rmax[2*mt],   fmaxf(c[0], c[1]));
                    rmax[2*mt+1] = fmaxf(rmax[2*mt+1], fmaxf(c[2], c[3]));
                    v[2*nt]   = fmaxf(v[2*nt],
                                fmaxf(c[0]*pxv[2*mt], c[2]*pxv[2*mt+1]));
                    v[2*nt+1] = fmaxf(v[2*nt+1],
                                fmaxf(c[1]*pxv[2*mt], c[3]*pxv[2*mt+1]));
                }

            // ---- reduce-scatter col MAX across the 8 duplicate lanes
#pragma unroll
            for (int q = 0; q < 4; q++) {
                float x = b16 ? v[q] : v[q + 4];
                float r = __shfl_xor_sync(0xffffffffu, x, 16);
                if (b16) v[q + 4] = fmaxf(v[q + 4], r);
                else     v[q]     = fmaxf(v[q], r);
            }
#pragma unroll
            for (int g = 0; g < 8; g += 4)
#pragma unroll
                for (int q = 0; q < 2; q++) {
                    float x = b8 ? v[g + q] : v[g + q + 2];
                    float r = __shfl_xor_sync(0xffffffffu, x, 8);
                    if (b8) v[g + q + 2] = fmaxf(v[g + q + 2], r);
                    else    v[g + q]     = fmaxf(v[g + q], r);
                }
#pragma unroll
            for (int g = 0; g < 8; g += 2) {
                float x = b4 ? v[g] : v[g + 1];
                float r = __shfl_xor_sync(0xffffffffu, x, 4);
                if (b4) v[g + 1] = fmaxf(v[g + 1], r);
                else    v[g]     = fmaxf(v[g], r);
            }
            float owned = b16 ? (b8 ? (b4 ? v[7] : v[6]) : (b4 ? v[5] : v[4]))
                              : (b8 ? (b4 ? v[3] : v[2]) : (b4 ? v[1] : v[0]));
            atomicMin(&g_colmin[jc0 + jt + 64*wc + 32*h + ownCol],
                      __float_as_int(fmaxf(-owned, 0.0f)));
        }
    }

    // ---- sweep epilogue: row maxes -> clamped mins
    float* rowp = (float*)(smem + SM_ROW);       // [2][128]
#pragma unroll
    for (int k = 0; k < 4; k++) {
        float v = rmax[k];
        v = fmaxf(v, __shfl_xor_sync(0xffffffffu, v, 1));
        v = fmaxf(v, __shfl_xor_sync(0xffffffffu, v, 2));
        if ((lane & 3) == 0)
            rowp[wc*128 + 32*wr + 16*(k >> 1) + 8*(k & 1) + (lane >> 2)] = v;
    }
    __syncthreads();
    if (tid < 128) {
        float rv = fmaxf(rowp[tid], rowp[128 + tid]);
        atomicMin(&g_rowmin[i0 + tid], __float_as_int(fmaxf(-rv, 0.0f)));
    }
}

// ---------------------------------------------------------------- finalize
__global__ void finalize_kernel(int N, int M, float* out) {
    __shared__ float red[256];
    __shared__ int   lastFlag;
    int  b     = blockIdx.x;
    bool isRow = (b < 64);
    int  idx   = (isRow ? b : b - 64) * 256 + threadIdx.x;
    float val  = 0.0f;
    int   lim  = isRow ? N : M;
    if (idx < lim) {
        float m = fmaxf(__int_as_float(isRow ? g_rowmin[idx] : g_colmin[idx]),
                        0.0f);
        // row: m = min_j sqdist*invy/2 -> u = 1 + 4*invx*m
        // col: m = min_i sqdist*invx*invy/2 -> u = 1 + 4*m
        float u = isRow ? fmaf(4.0f * m, g_invx[idx], 1.0f)
                        : fmaf(4.0f, m, 1.0f);
        val = logf(u + sqrtf(fmaxf(u * u - 1.0f, 0.0f)));
    }
    red[threadIdx.x] = val;
    __syncthreads();
    for (int s = 128; s > 0; s >>= 1) {
        if (threadIdx.x < s) red[threadIdx.x] += red[threadIdx.x + s];
        __syncthreads();
    }
    if (threadIdx.x == 0) {
        g_part[b] = red[0] * (isRow ? 1.0f / (float)N : 1.0f / (float)M);
        __threadfence();
        int t = atomicAdd(&g_done, 1);
        lastFlag = (t == 127);
    }
    __syncthreads();
    if (lastFlag) {
        red[threadIdx.x] = (threadIdx.x < 128) ? g_part[threadIdx.x] : 0.0f;
        __syncthreads();
        for (int s = 128; s > 0; s >>= 1) {
            if (threadIdx.x < s) red[threadIdx.x] += red[threadIdx.x + s];
            __syncthreads();
        }
        if (threadIdx.x == 0) out[0] = red[0];
    }
}

// ---------------------------------------------------------------- launch
extern "C" void kernel_launch(void* const* d_in, const int* in_sizes, int n_in,
                              void* d_out, int out_size) {
    const float* X = (const float*)d_in[0];
    const float* Y = (const float*)d_in[1];
    int N = in_sizes[0] / 16;
    int M = in_sizes[1] / 16;

    static int configured = 0;
    if (!configured) {
        cudaFuncSetAttribute(pair_mma_kernel,
                             cudaFuncAttributeMaxDynamicSharedMemorySize,
                             SM_TOT);
        configured = 1;
    }

    prep_kernel<<<256, 128>>>(X, Y, N, M);

    dim3 grid(M / 1024, N / 128);
    pair_mma_kernel<<<grid, 256, SM_TOT>>>();

    finalize_kernel<<<128, 256>>>(N, M, (float*)d_out);
}

// round 12
// speedup vs baseline: 1.3266x; 1.0531x over previous
#include <cuda_runtime.h>
#include <cuda_bf16.h>
#include <cstdint>

// ============================================================================
// Hyperbolic averaged Hausdorff loss via tensor-core mma.sync (bf16).
// (build targets plain sm_103: tcgen05 unavailable; legacy HMMA path)
//
// R12: BOTH inverse factors folded into the GEMM.
//   A'_i = x_i*invx_i (hi/lo split), B'_j = y_j*invy_j (hi/lo split)
//   fold cols (6): A [P_h,P_h,P_l,Q_h,Q_h,Q_l]  P=xn*invx, Q=invx
//                  B [C_h,C_l,C_h,D_h,D_l,D_h]  C=-invy/2, D=-yn*invy/2
//   => acc_ij = invx*invy*(dot - (xn+yn)/2) = -sqdist*invx*invy/2
//   u_ij = 1 + 2*sqdist*invx*invy = 1 - 4*acc   (monotone in acc)
//   row & col mins == max_j/max_i acc  ->  epilogue = 2 FMNMX/elem, no MUL.
//   finalize: m = max(-acc_max, 0); u = 1 + 4m; d = arcosh(u).
// Persistent-A sweep, cp.async double buffer, 1 barrier/tile, reduce-scatter
// col reduction with direct lane atomics.
// ============================================================================

#define NPTS 16384
#define TILES_PER_SWEEP 8

__device__ int   g_rowmin[NPTS], g_colmin[NPTS];
__device__ float g_part[128];
__device__ int   g_done;
__device__ __nv_bfloat16 g_A[NPTS * 64];
__device__ __nv_bfloat16 g_B[NPTS * 64];

__device__ __forceinline__ uint32_t smem_u32(const void* p) {
    uint32_t a;
    asm("{ .reg .u64 t; cvta.to.shared.u64 t, %1; cvt.u32.u64 %0, t; }"
        : "=r"(a) : "l"(p));
    return a;
}
#define SMEM_SWZ(o) ((o) ^ ((((o) >> 3) & 0x70)))

#define CPASYNC16(dst, src) \
    asm volatile("cp.async.cg.shared.global [%0], [%1], 16;" \
                 :: "r"(dst), "l"(src))
#define CPCOMMIT() asm volatile("cp.async.commit_group;")
#define CPWAIT0()  asm volatile("cp.async.wait_group 0;")

#define LDSM4(r, addr)                                                      \
    asm volatile("ldmatrix.sync.aligned.m8n8.x4.shared.b16 "                \
                 "{%0,%1,%2,%3}, [%4];"                                     \
                 : "=r"((r)[0]), "=r"((r)[1]), "=r"((r)[2]), "=r"((r)[3])   \
                 : "r"(addr))

#define MMA16816(d, a, b0, b1)                                              \
    asm volatile("mma.sync.aligned.m16n8k16.row.col.f32.bf16.bf16.f32 "     \
                 "{%0,%1,%2,%3}, {%4,%5,%6,%7}, {%8,%9}, {%0,%1,%2,%3};"    \
                 : "+f"((d)[0]), "+f"((d)[1]), "+f"((d)[2]), "+f"((d)[3])   \
                 : "r"((a)[0]), "r"((a)[1]), "r"((a)[2]), "r"((a)[3]),      \
                   "r"(b0), "r"(b1))

// ---------------------------------------------------------------- smem layout
#define SM_A    0                       // 16384   (128 rows x 128B)
#define SM_B    16384                   // 2 x 16384 -> ends 49152
#define SM_ROW  49152                   // 2 x 128 x f32 = 1024
#define SM_TOT  50176

// ---------------------------------------------------------------- prep kernel
union BU { __nv_bfloat16 b; unsigned short u; };
__device__ __forceinline__ unsigned short bfu(float x) {
    BU t; t.b = __float2bfloat16(x); return t.u;
}
__device__ __forceinline__ float bff(unsigned short u) {
    BU t; t.u = u; return __bfloat162float(t.b);
}

__device__ __forceinline__ void split_store(const float* src, int idx,
                                            __nv_bfloat16* dst, bool isA,
                                            int* mn) {
    float v[16];
    const float4* p = (const float4*)(src + (size_t)idx * 16);
    float4 q0 = p[0], q1 = p[1], q2 = p[2], q3 = p[3];
    v[0]=q0.x; v[1]=q0.y; v[2]=q0.z; v[3]=q0.w;
    v[4]=q1.x; v[5]=q1.y; v[6]=q1.z; v[7]=q1.w;
    v[8]=q2.x; v[9]=q2.y; v[10]=q2.z; v[11]=q2.w;
    v[12]=q3.x; v[13]=q3.y; v[14]=q3.z; v[15]=q3.w;
    float s = 0.f;
#pragma unroll
    for (int d = 0; d < 16; d++) s += v[d] * v[d];
    float inv = 1.0f / (1.0f - s);
    mn[idx] = 0x7f800000;

    // scale data by inv on BOTH sides
#pragma unroll
    for (int d = 0; d < 16; d++) v[d] *= inv;

    unsigned short hi[16], lo[16];
#pragma unroll
    for (int d = 0; d < 16; d++) {
        hi[d] = bfu(v[d]);
        lo[d] = bfu(v[d] - bff(hi[d]));
    }
    uint32_t w[32];
#pragma unroll
    for (int k = 0; k < 8; k++) {
        uint32_t hp = (uint32_t)hi[2*k] | ((uint32_t)hi[2*k+1] << 16);
        uint32_t lp = (uint32_t)lo[2*k] | ((uint32_t)lo[2*k+1] << 16);
        w[k]      = hp;
        w[8 + k]  = isA ? lp : hp;
        w[16 + k] = isA ? hp : lp;
    }
    // fold columns 48..53 (product splits):
    //  A: [P_h, P_h, P_l, Q_h, Q_h, Q_l]   P = xn*invx, Q = invx
    //  B: [C_h, C_l, C_h, D_h, D_l, D_h]   C = -invy/2, D = -yn*invy/2
    if (isA) {
        float P = s * inv;
        unsigned short Ph = bfu(P), Pl = bfu(P - bff(Ph));
        unsigned short Qh = bfu(inv), Ql = bfu(inv - bff(Qh));
        w[24] = (uint32_t)Ph | ((uint32_t)Ph << 16);
        w[25] = (uint32_t)Pl | ((uint32_t)Qh << 16);
        w[26] = (uint32_t)Qh | ((uint32_t)Ql << 16);
    } else {
        float C = -0.5f * inv;
        unsigned short Ch = bfu(C), Cl = bfu(C - bff(Ch));
        float D = -0.5f * s * inv;
        unsigned short Dh = bfu(D), Dl = bfu(D - bff(Dh));
        w[24] = (uint32_t)Ch | ((uint32_t)Cl << 16);
        w[25] = (uint32_t)Ch | ((uint32_t)Dh << 16);
        w[26] = (uint32_t)Dl | ((uint32_t)Dh << 16);
    }
#pragma unroll
    for (int k = 27; k < 32; k++) w[k] = 0u;

    uint4* d4 = (uint4*)(dst + (size_t)idx * 64);
#pragma unroll
    for (int c = 0; c < 8; c++)
        d4[c] = make_uint4(w[4*c], w[4*c+1], w[4*c+2], w[4*c+3]);
}

// 256 blocks x 128 threads: blocks [0,128) X, [128,256) Y
__global__ void prep_kernel(const float* __restrict__ X,
                            const float* __restrict__ Y, int N, int M) {
    int b = blockIdx.x;
    if (b == 0 && threadIdx.x == 0) g_done = 0;
    if (b < 128) {
        int idx = b * 128 + threadIdx.x;
        if (idx < N) split_store(X, idx, g_A, true,  g_rowmin);
    } else {
        int idx = (b - 128) * 128 + threadIdx.x;
        if (idx < M) split_store(Y, idx, g_B, false, g_colmin);
    }
}

// ---------------------------------------------------------------- pair kernel
__global__ void __launch_bounds__(256, 2) pair_mma_kernel() {
    extern __shared__ __align__(16) char smem[];
    const uint32_t sb = smem_u32(smem);

    const int tid  = threadIdx.x;
    const int wid  = tid >> 5;
    const int lane = tid & 31;
    const int i0   = blockIdx.y * 128;
    const int jc0  = blockIdx.x * 1024;          // chunk base column

    const int wr = wid & 3;
    const int wc = wid >> 2;
    const int lr = lane & 15;
    const int lc = lane >> 4;
    const float NINF = __int_as_float(0xff800000);

    const int cr = tid >> 3, cc = tid & 7;       // 16B-chunk coords (4/thread)
    const uint32_t swz0 = SMEM_SWZ(cr * 128 + cc * 16);
    const uint32_t swz1 = SMEM_SWZ((cr + 32) * 128 + cc * 16);
    const uint32_t swz2 = SMEM_SWZ((cr + 64) * 128 + cc * 16);
    const uint32_t swz3 = SMEM_SWZ((cr + 96) * 128 + cc * 16);
    const size_t   goff = (size_t)cr * 128 + cc * 16;

    // ---- prologue: async-copy A tile + B tile 0
    {
        const char* Ag = (const char*)g_A + (size_t)i0 * 128;
        CPASYNC16(sb + SM_A + swz0, Ag + goff);
        CPASYNC16(sb + SM_A + swz1, Ag + goff + 32 * 128);
        CPASYNC16(sb + SM_A + swz2, Ag + goff + 64 * 128);
        CPASYNC16(sb + SM_A + swz3, Ag + goff + 96 * 128);
        const char* Bg = (const char*)g_B + (size_t)jc0 * 128;
        CPASYNC16(sb + SM_B + swz0, Bg + goff);
        CPASYNC16(sb + SM_B + swz1, Bg + goff + 32 * 128);
        CPASYNC16(sb + SM_B + swz2, Bg + goff + 64 * 128);
        CPASYNC16(sb + SM_B + swz3, Bg + goff + 96 * 128);
        CPCOMMIT();
    }

    CPWAIT0();
    __syncthreads();

    // ---- A fragments once per sweep
    uint32_t afr[4][2][4];
#pragma unroll
    for (int ks = 0; ks < 4; ks++)
#pragma unroll
        for (int mt = 0; mt < 2; mt++) {
            int row = 32*wr + 16*mt + lr;
            LDSM4(afr[ks][mt], sb + SM_A + SMEM_SWZ(row*128 + ks*32 + lc*16));
        }

    // prefetch B tile 1
    {
        const char* Bg = (const char*)g_B + (size_t)(jc0 + 128) * 128;
        uint32_t d = sb + SM_B + 16384;
        CPASYNC16(d + swz0, Bg + goff);
        CPASYNC16(d + swz1, Bg + goff + 32 * 128);
        CPASYNC16(d + swz2, Bg + goff + 64 * 128);
        CPASYNC16(d + swz3, Bg + goff + 96 * 128);
        CPCOMMIT();
    }

    float rmax[4] = {NINF, NINF, NINF, NINF};

    const int b16 = (lane >> 4) & 1;
    const int b8  = (lane >> 3) & 1;
    const int b4  = (lane >> 2) & 1;
    const int ownCol = 8 * (2 * b16 + b8) + 2 * (lane & 3) + b4;

#pragma unroll 1
    for (int t = 0; t < TILES_PER_SWEEP; t++) {
        if (t > 0) {
            CPWAIT0();
            __syncthreads();
            if (t + 1 < TILES_PER_SWEEP) {
                const char* Bg =
                    (const char*)g_B + (size_t)(jc0 + (t + 1) * 128) * 128;
                uint32_t d = sb + SM_B + ((t + 1) & 1) * 16384;
                CPASYNC16(d + swz0, Bg + goff);
                CPASYNC16(d + swz1, Bg + goff + 32 * 128);
                CPASYNC16(d + swz2, Bg + goff + 64 * 128);
                CPASYNC16(d + swz3, Bg + goff + 96 * 128);
                CPCOMMIT();
            }
        }

        const uint32_t sBb = sb + SM_B + (t & 1) * 16384;
        const int jt = t * 128;

#pragma unroll
        for (int h = 0; h < 2; h++) {
            float acc[2][4][4];
#pragma unroll
            for (int mt = 0; mt < 2; mt++)
#pragma unroll
                for (int nt = 0; nt < 4; nt++)
#pragma unroll
                    for (int e = 0; e < 4; e++) acc[mt][nt][e] = 0.0f;

#pragma unroll
            for (int ks = 0; ks < 4; ks++) {
                uint32_t b[2][4];
#pragma unroll
                for (int np = 0; np < 2; np++) {
                    int row = 64*wc + 32*h + 16*np + lr;
                    LDSM4(b[np], sBb + SMEM_SWZ(row*128 + ks*32 + lc*16));
                }
#pragma unroll
                for (int mt = 0; mt < 2; mt++)
#pragma unroll
                    for (int nt = 0; nt < 4; nt++) {
                        int np = nt >> 1, od = nt & 1;
                        MMA16816(acc[mt][nt], afr[ks][mt], b[np][od], b[np][od+2]);
                    }
            }

            // ---- epilogue: 2 FMNMX per element, zero MULs
            float v[8];
#pragma unroll
            for (int k = 0; k < 8; k++) v[k] = NINF;
#pragma unroll
            for (int mt = 0; mt < 2; mt++)
#pragma unroll
                for (int nt = 0; nt < 4; nt++) {
                    float* c = acc[mt][nt];
                    rmax[2*mt]   = fmaxf(rmax[2*mt],   fmaxf(c[0], c[1]));
                    rmax[2*mt+1] = fmaxf(rmax[2*mt+1], fmaxf(c[2], c[3]));
                    v[2*nt]   = fmaxf(v[2*nt],   fmaxf(c[0], c[2]));
                    v[2*nt+1] = fmaxf(v[2*nt+1], fmaxf(c[1], c[3]));
                }

            // ---- reduce-scatter col MAX across the 8 duplicate lanes
#pragma unroll
            for (int q = 0; q < 4; q++) {
                float x = b16 ? v[q] : v[q + 4];
                float r = __shfl_xor_sync(0xffffffffu, x, 16);
                if (b16) v[q + 4] = fmaxf(v[q + 4], r);
                else     v[q]     = fmaxf(v[q], r);
            }
#pragma unroll
            for (int g = 0; g < 8; g += 4)
#pragma unroll
                for (int q = 0; q < 2; q++) {
                    float x = b8 ? v[g + q] : v[g + q + 2];
                    float r = __shfl_xor_sync(0xffffffffu, x, 8);
                    if (b8) v[g + q + 2] = fmaxf(v[g + q + 2], r);
                    else    v[g + q]     = fmaxf(v[g + q], r);
                }
#pragma unroll
            for (int g = 0; g < 8; g += 2) {
                float x = b4 ? v[g] : v[g + 1];
                float r = __shfl_xor_sync(0xffffffffu, x, 4);
                if (b4) v[g + 1] = fmaxf(v[g + 1], r);
                else    v[g]     = fmaxf(v[g], r);
            }
            float owned = b16 ? (b8 ? (b4 ? v[7] : v[6]) : (b4 ? v[5] : v[4]))
                              : (b8 ? (b4 ? v[3] : v[2]) : (b4 ? v[1] : v[0]));
            atomicMin(&g_colmin[jc0 + jt + 64*wc + 32*h + ownCol],
                      __float_as_int(fmaxf(-owned, 0.0f)));
        }
    }

    // ---- sweep epilogue: row maxes -> clamped mins
    float* rowp = (float*)(smem + SM_ROW);       // [2][128]
#pragma unroll
    for (int k = 0; k < 4; k++) {
        float v = rmax[k];
        v = fmaxf(v, __shfl_xor_sync(0xffffffffu, v, 1));
        v = fmaxf(v, __shfl_xor_sync(0xffffffffu, v, 2));
        if ((lane & 3) == 0)
            rowp[wc*128 + 32*wr + 16*(k >> 1) + 8*(k & 1) + (lane >> 2)] = v;
    }
    __syncthreads();
    if (tid < 128) {
        float rv = fmaxf(rowp[tid], rowp[128 + tid]);
        atomicMin(&g_rowmin[i0 + tid], __float_as_int(fmaxf(-rv, 0.0f)));
    }
}

// ---------------------------------------------------------------- finalize
__global__ void finalize_kernel(int N, int M, float* out) {
    __shared__ float red[256];
    __shared__ int   lastFlag;
    int  b     = blockIdx.x;
    bool isRow = (b < 64);
    int  idx   = (isRow ? b : b - 64) * 256 + threadIdx.x;
    float val  = 0.0f;
    int   lim  = isRow ? N : M;
    if (idx < lim) {
        float m = fmaxf(__int_as_float(isRow ? g_rowmin[idx] : g_colmin[idx]),
                        0.0f);
        // m = min (sqdist*invx*invy)/2  ->  u = 1 + 2*sqdist*ixy = 1 + 4m
        float u = fmaf(4.0f, m, 1.0f);
        val = logf(u + sqrtf(fmaxf(u * u - 1.0f, 0.0f)));
    }
    red[threadIdx.x] = val;
    __syncthreads();
    for (int s = 128; s > 0; s >>= 1) {
        if (threadIdx.x < s) red[threadIdx.x] += red[threadIdx.x + s];
        __syncthreads();
    }
    if (threadIdx.x == 0) {
        g_part[b] = red[0] * (isRow ? 1.0f / (float)N : 1.0f / (float)M);
        __threadfence();
        int t = atomicAdd(&g_done, 1);
        lastFlag = (t == 127);
    }
    __syncthreads();
    if (lastFlag) {
        red[threadIdx.x] = (threadIdx.x < 128) ? g_part[threadIdx.x] : 0.0f;
        __syncthreads();
        for (int s = 128; s > 0; s >>= 1) {
            if (threadIdx.x < s) red[threadIdx.x] += red[threadIdx.x + s];
            __syncthreads();
        }
        if (threadIdx.x == 0) out[0] = red[0];
    }
}

// ---------------------------------------------------------------- launch
extern "C" void kernel_launch(void* const* d_in, const int* in_sizes, int n_in,
                              void* d_out, int out_size) {
    const float* X = (const float*)d_in[0];
    const float* Y = (const float*)d_in[1];
    int N = in_sizes[0] / 16;
    int M = in_sizes[1] / 16;

    static int configured = 0;
    if (!configured) {
        cudaFuncSetAttribute(pair_mma_kernel,
                             cudaFuncAttributeMaxDynamicSharedMemorySize,
                             SM_TOT);
        configured = 1;
    }

    prep_kernel<<<256, 128>>>(X, Y, N, M);

    dim3 grid(M / 1024, N / 128);
    pair_mma_kernel<<<grid, 256, SM_TOT>>>();

    finalize_kernel<<<128, 256>>>(N, M, (float*)d_out);
}

// round 13
// speedup vs baseline: 1.3951x; 1.0517x over previous
#include <cuda_runtime.h>
#include <cuda_bf16.h>
#include <cstdint>

// ============================================================================
// Hyperbolic averaged Hausdorff loss via tensor-core mma.sync (bf16).
// (build targets plain sm_103: tcgen05 unavailable; legacy HMMA path)
//
// R13 = R12 (both inverse factors folded into the GEMM; epilogue = 2 FMNMX
// per element) with:
//   - 4th k-step m16n8k16 -> m16n8k8 over the fold cols 48..55 (data occupies
//     exactly cols 0..47): same MMA instruction count, tensor-pipe time -12.5%
//   - A tile split computed in the pair prologue from X directly (g_A gone);
//     prep kernel handles only Y
// Math: acc_ij = invx*invy*(dot - (xn+yn)/2) = -sqdist*invx*invy/2
//       u = 1 - 4*acc (monotone) -> row/col mins are plain max(acc).
// ============================================================================

#define NPTS 16384
#define TILES_PER_SWEEP 8

__device__ int   g_rowmin[NPTS], g_colmin[NPTS];
__device__ float g_part[128];
__device__ int   g_done;
__device__ __nv_bfloat16 g_B[NPTS * 64];

__device__ __forceinline__ uint32_t smem_u32(const void* p) {
    uint32_t a;
    asm("{ .reg .u64 t; cvta.to.shared.u64 t, %1; cvt.u32.u64 %0, t; }"
        : "=r"(a) : "l"(p));
    return a;
}
#define SMEM_SWZ(o) ((o) ^ ((((o) >> 3) & 0x70)))

#define CPASYNC16(dst, src) \
    asm volatile("cp.async.cg.shared.global [%0], [%1], 16;" \
                 :: "r"(dst), "l"(src))
#define CPCOMMIT() asm volatile("cp.async.commit_group;")
#define CPWAIT0()  asm volatile("cp.async.wait_group 0;")

#define LDSM4(r, addr)                                                      \
    asm volatile("ldmatrix.sync.aligned.m8n8.x4.shared.b16 "                \
                 "{%0,%1,%2,%3}, [%4];"                                     \
                 : "=r"((r)[0]), "=r"((r)[1]), "=r"((r)[2]), "=r"((r)[3])   \
                 : "r"(addr))

#define MMA16816(d, a, b0, b1)                                              \
    asm volatile("mma.sync.aligned.m16n8k16.row.col.f32.bf16.bf16.f32 "     \
                 "{%0,%1,%2,%3}, {%4,%5,%6,%7}, {%8,%9}, {%0,%1,%2,%3};"    \
                 : "+f"((d)[0]), "+f"((d)[1]), "+f"((d)[2]), "+f"((d)[3])   \
                 : "r"((a)[0]), "r"((a)[1]), "r"((a)[2]), "r"((a)[3]),      \
                   "r"(b0), "r"(b1))

#define MMA16808(d, a0, a1, b0)                                             \
    asm volatile("mma.sync.aligned.m16n8k8.row.col.f32.bf16.bf16.f32 "      \
                 "{%0,%1,%2,%3}, {%4,%5}, {%6}, {%0,%1,%2,%3};"             \
                 : "+f"((d)[0]), "+f"((d)[1]), "+f"((d)[2]), "+f"((d)[3])   \
                 : "r"(a0), "r"(a1), "r"(b0))

// ---------------------------------------------------------------- smem layout
#define SM_A    0                       // 16384   (128 rows x 128B)
#define SM_B    16384                   // 2 x 16384 -> ends 49152
#define SM_ROW  49152                   // 2 x 128 x f32 = 1024
#define SM_TOT  50176

// --------------------------------------------------------------- split helpers
union BU { __nv_bfloat16 b; unsigned short u; };
__device__ __forceinline__ unsigned short bfu(float x) {
    BU t; t.b = __float2bfloat16(x); return t.u;
}
__device__ __forceinline__ float bff(unsigned short u) {
    BU t; t.u = u; return __bfloat162float(t.b);
}

// Build the 64-col bf16 row (w[32] packed pairs) for one point.
// isA: A layout [hi | lo | hi | P_h,P_h,P_l,Q_h,Q_h,Q_l | 0...]
// else B layout [hi | hi | lo | C_h,C_l,C_h,D_h,D_l,D_h | 0...]
__device__ __forceinline__ void build_row(const float* __restrict__ src,
                                          bool isA, uint32_t* w) {
    float v[16];
    const float4* p = (const float4*)src;
    float4 q0 = p[0], q1 = p[1], q2 = p[2], q3 = p[3];
    v[0]=q0.x; v[1]=q0.y; v[2]=q0.z; v[3]=q0.w;
    v[4]=q1.x; v[5]=q1.y; v[6]=q1.z; v[7]=q1.w;
    v[8]=q2.x; v[9]=q2.y; v[10]=q2.z; v[11]=q2.w;
    v[12]=q3.x; v[13]=q3.y; v[14]=q3.z; v[15]=q3.w;
    float s = 0.f;
#pragma unroll
    for (int d = 0; d < 16; d++) s += v[d] * v[d];
    float inv = 1.0f / (1.0f - s);
#pragma unroll
    for (int d = 0; d < 16; d++) v[d] *= inv;

    unsigned short hi[16], lo[16];
#pragma unroll
    for (int d = 0; d < 16; d++) {
        hi[d] = bfu(v[d]);
        lo[d] = bfu(v[d] - bff(hi[d]));
    }
#pragma unroll
    for (int k = 0; k < 8; k++) {
        uint32_t hp = (uint32_t)hi[2*k] | ((uint32_t)hi[2*k+1] << 16);
        uint32_t lp = (uint32_t)lo[2*k] | ((uint32_t)lo[2*k+1] << 16);
        w[k]      = hp;
        w[8 + k]  = isA ? lp : hp;
        w[16 + k] = isA ? hp : lp;
    }
    if (isA) {
        float P = s * inv;
        unsigned short Ph = bfu(P), Pl = bfu(P - bff(Ph));
        unsigned short Qh = bfu(inv), Ql = bfu(inv - bff(Qh));
        w[24] = (uint32_t)Ph | ((uint32_t)Ph << 16);
        w[25] = (uint32_t)Pl | ((uint32_t)Qh << 16);
        w[26] = (uint32_t)Qh | ((uint32_t)Ql << 16);
    } else {
        float C = -0.5f * inv;
        unsigned short Ch = bfu(C), Cl = bfu(C - bff(Ch));
        float D = -0.5f * s * inv;
        unsigned short Dh = bfu(D), Dl = bfu(D - bff(Dh));
        w[24] = (uint32_t)Ch | ((uint32_t)Cl << 16);
        w[25] = (uint32_t)Ch | ((uint32_t)Dh << 16);
        w[26] = (uint32_t)Dl | ((uint32_t)Dh << 16);
    }
#pragma unroll
    for (int k = 27; k < 32; k++) w[k] = 0u;
}

// ---------------------------------------------------------------- prep kernel
// Y-only: 128 blocks x 128 threads.
__global__ void prep_kernel(const float* __restrict__ Y, int N, int M) {
    int idx = blockIdx.x * 128 + threadIdx.x;
    if (idx == 0) g_done = 0;
    if (idx < N) g_rowmin[idx] = 0x7f800000;
    if (idx < M) {
        g_colmin[idx] = 0x7f800000;
        uint32_t w[32];
        build_row(Y + (size_t)idx * 16, false, w);
        uint4* d4 = (uint4*)(g_B + (size_t)idx * 64);
#pragma unroll
        for (int c = 0; c < 8; c++)
            d4[c] = make_uint4(w[4*c], w[4*c+1], w[4*c+2], w[4*c+3]);
    }
}

// ---------------------------------------------------------------- pair kernel
__global__ void __launch_bounds__(256, 2) pair_mma_kernel(
        const float* __restrict__ X) {
    extern __shared__ __align__(16) char smem[];
    const uint32_t sb = smem_u32(smem);

    const int tid  = threadIdx.x;
    const int wid  = tid >> 5;
    const int lane = tid & 31;
    const int i0   = blockIdx.y * 128;
    const int jc0  = blockIdx.x * 1024;          // chunk base column

    const int wr = wid & 3;
    const int wc = wid >> 2;
    const int lr = lane & 15;
    const int lc = lane >> 4;
    const float NINF = __int_as_float(0xff800000);

    const int cr = tid >> 3, cc = tid & 7;       // 16B-chunk coords (4/thread)
    const uint32_t swz0 = SMEM_SWZ(cr * 128 + cc * 16);
    const uint32_t swz1 = SMEM_SWZ((cr + 32) * 128 + cc * 16);
    const uint32_t swz2 = SMEM_SWZ((cr + 64) * 128 + cc * 16);
    const uint32_t swz3 = SMEM_SWZ((cr + 96) * 128 + cc * 16);
    const size_t   goff = (size_t)cr * 128 + cc * 16;

    // ---- prologue: async-copy B tile 0; A tile computed from X in-place
    {
        const char* Bg = (const char*)g_B + (size_t)jc0 * 128;
        CPASYNC16(sb + SM_B + swz0, Bg + goff);
        CPASYNC16(sb + SM_B + swz1, Bg + goff + 32 * 128);
        CPASYNC16(sb + SM_B + swz2, Bg + goff + 64 * 128);
        CPASYNC16(sb + SM_B + swz3, Bg + goff + 96 * 128);
        CPCOMMIT();
    }
    if (tid < 128) {
        uint32_t w[32];
        build_row(X + (size_t)(i0 + tid) * 16, true, w);
#pragma unroll
        for (int c = 0; c < 8; c++)
            *(uint4*)(smem + SM_A + SMEM_SWZ(tid * 128 + c * 16)) =
                make_uint4(w[4*c], w[4*c+1], w[4*c+2], w[4*c+3]);
    }

    CPWAIT0();
    __syncthreads();

    // ---- A fragments once per sweep: 3 k16 steps + 1 k8 fold step
    uint32_t afr[3][2][4];
#pragma unroll
    for (int ks = 0; ks < 3; ks++)
#pragma unroll
        for (int mt = 0; mt < 2; mt++) {
            int row = 32*wr + 16*mt + lr;
            LDSM4(afr[ks][mt], sb + SM_A + SMEM_SWZ(row*128 + ks*32 + lc*16));
        }
    uint32_t afr8[4];    // [mt0: rows 0-7, 8-15][mt1: rows 16-23, 24-31]
    LDSM4(afr8, sb + SM_A + SMEM_SWZ((32*wr + lane)*128 + 96));

    // prefetch B tile 1
    {
        const char* Bg = (const char*)g_B + (size_t)(jc0 + 128) * 128;
        uint32_t d = sb + SM_B + 16384;
        CPASYNC16(d + swz0, Bg + goff);
        CPASYNC16(d + swz1, Bg + goff + 32 * 128);
        CPASYNC16(d + swz2, Bg + goff + 64 * 128);
        CPASYNC16(d + swz3, Bg + goff + 96 * 128);
        CPCOMMIT();
    }

    float rmax[4] = {NINF, NINF, NINF, NINF};

    const int b16 = (lane >> 4) & 1;
    const int b8  = (lane >> 3) & 1;
    const int b4  = (lane >> 2) & 1;
    const int ownCol = 8 * (2 * b16 + b8) + 2 * (lane & 3) + b4;

#pragma unroll 1
    for (int t = 0; t < TILES_PER_SWEEP; t++) {
        if (t > 0) {
            CPWAIT0();
            __syncthreads();
            if (t + 1 < TILES_PER_SWEEP) {
                const char* Bg =
                    (const char*)g_B + (size_t)(jc0 + (t + 1) * 128) * 128;
                uint32_t d = sb + SM_B + ((t + 1) & 1) * 16384;
                CPASYNC16(d + swz0, Bg + goff);
                CPASYNC16(d + swz1, Bg + goff + 32 * 128);
                CPASYNC16(d + swz2, Bg + goff + 64 * 128);
                CPASYNC16(d + swz3, Bg + goff + 96 * 128);
                CPCOMMIT();
            }
        }

        const uint32_t sBb = sb + SM_B + (t & 1) * 16384;
        const int jt = t * 128;

#pragma unroll
        for (int h = 0; h < 2; h++) {
            float acc[2][4][4];
#pragma unroll
            for (int mt = 0; mt < 2; mt++)
#pragma unroll
                for (int nt = 0; nt < 4; nt++)
#pragma unroll
                    for (int e = 0; e < 4; e++) acc[mt][nt][e] = 0.0f;

            // 3 full k16 steps over data cols 0..47
#pragma unroll
            for (int ks = 0; ks < 3; ks++) {
                uint32_t b[2][4];
#pragma unroll
                for (int np = 0; np < 2; np++) {
                    int row = 64*wc + 32*h + 16*np + lr;
                    LDSM4(b[np], sBb + SMEM_SWZ(row*128 + ks*32 + lc*16));
                }
#pragma unroll
                for (int mt = 0; mt < 2; mt++)
#pragma unroll
                    for (int nt = 0; nt < 4; nt++) {
                        int np = nt >> 1, od = nt & 1;
                        MMA16816(acc[mt][nt], afr[ks][mt], b[np][od], b[np][od+2]);
                    }
            }
            // k8 fold step over cols 48..55 (half tensor occupancy)
            {
                uint32_t bf8[4];
                LDSM4(bf8, sBb + SMEM_SWZ((64*wc + 32*h + lane)*128 + 96));
#pragma unroll
                for (int mt = 0; mt < 2; mt++)
#pragma unroll
                    for (int nt = 0; nt < 4; nt++)
                        MMA16808(acc[mt][nt], afr8[2*mt], afr8[2*mt+1], bf8[nt]);
            }

            // ---- epilogue: 2 FMNMX per element, zero MULs
            float v[8];
#pragma unroll
            for (int k = 0; k < 8; k++) v[k] = NINF;
#pragma unroll
            for (int mt = 0; mt < 2; mt++)
#pragma unroll
                for (int nt = 0; nt < 4; nt++) {
                    float* c = acc[mt][nt];
                    rmax[2*mt]   = fmaxf(rmax[2*mt],   fmaxf(c[0], c[1]));
                    rmax[2*mt+1] = fmaxf(rmax[2*mt+1], fmaxf(c[2], c[3]));
                    v[2*nt]   = fmaxf(v[2*nt],   fmaxf(c[0], c[2]));
                    v[2*nt+1] = fmaxf(v[2*nt+1], fmaxf(c[1], c[3]));
                }

            // ---- reduce-scatter col MAX across the 8 duplicate lanes
#pragma unroll
            for (int q = 0; q < 4; q++) {
                float x = b16 ? v[q] : v[q + 4];
                float r = __shfl_xor_sync(0xffffffffu, x, 16);
                if (b16) v[q + 4] = fmaxf(v[q + 4], r);
                else     v[q]     = fmaxf(v[q], r);
            }
#pragma unroll
            for (int g = 0; g < 8; g += 4)
#pragma unroll
                for (int q = 0; q < 2; q++) {
                    float x = b8 ? v[g + q] : v[g + q + 2];
                    float r = __shfl_xor_sync(0xffffffffu, x, 8);
                    if (b8) v[g + q + 2] = fmaxf(v[g + q + 2], r);
                    else    v[g + q]     = fmaxf(v[g + q], r);
                }
#pragma unroll
            for (int g = 0; g < 8; g += 2) {
                float x = b4 ? v[g] : v[g + 1];
                float r = __shfl_xor_sync(0xffffffffu, x, 4);
                if (b4) v[g + 1] = fmaxf(v[g + 1], r);
                else    v[g]     = fmaxf(v[g], r);
            }
            float owned = b16 ? (b8 ? (b4 ? v[7] : v[6]) : (b4 ? v[5] : v[4]))
                              : (b8 ? (b4 ? v[3] : v[2]) : (b4 ? v[1] : v[0]));
            atomicMin(&g_colmin[jc0 + jt + 64*wc + 32*h + ownCol],
                      __float_as_int(fmaxf(-owned, 0.0f)));
        }
    }

    // ---- sweep epilogue: row maxes -> clamped mins
    float* rowp = (float*)(smem + SM_ROW);       // [2][128]
#pragma unroll
    for (int k = 0; k < 4; k++) {
        float v = rmax[k];
        v = fmaxf(v, __shfl_xor_sync(0xffffffffu, v, 1));
        v = fmaxf(v, __shfl_xor_sync(0xffffffffu, v, 2));
        if ((lane & 3) == 0)
            rowp[wc*128 + 32*wr + 16*(k >> 1) + 8*(k & 1) + (lane >> 2)] = v;
    }
    __syncthreads();
    if (tid < 128) {
        float rv = fmaxf(rowp[tid], rowp[128 + tid]);
        atomicMin(&g_rowmin[i0 + tid], __float_as_int(fmaxf(-rv, 0.0f)));
    }
}

// ---------------------------------------------------------------- finalize
__global__ void finalize_kernel(int N, int M, float* out) {
    __shared__ float red[256];
    __shared__ int   lastFlag;
    int  b     = blockIdx.x;
    bool isRow = (b < 64);
    int  idx   = (isRow ? b : b - 64) * 256 + threadIdx.x;
    float val  = 0.0f;
    int   lim  = isRow ? N : M;
    if (idx < lim) {
        float m = fmaxf(__int_as_float(isRow ? g_rowmin[idx] : g_colmin[idx]),
                        0.0f);
        float u = fmaf(4.0f, m, 1.0f);
        val = logf(u + sqrtf(fmaxf(u * u - 1.0f, 0.0f)));
    }
    red[threadIdx.x] = val;
    __syncthreads();
    for (int s = 128; s > 0; s >>= 1) {
        if (threadIdx.x < s) red[threadIdx.x] += red[threadIdx.x + s];
        __syncthreads();
    }
    if (threadIdx.x == 0) {
        g_part[b] = red[0] * (isRow ? 1.0f / (float)N : 1.0f / (float)M);
        __threadfence();
        int t = atomicAdd(&g_done, 1);
        lastFlag = (t == 127);
    }
    __syncthreads();
    if (lastFlag) {
        red[threadIdx.x] = (threadIdx.x < 128) ? g_part[threadIdx.x] : 0.0f;
        __syncthreads();
        for (int s = 128; s > 0; s >>= 1) {
            if (threadIdx.x < s) red[threadIdx.x] += red[threadIdx.x + s];
            __syncthreads();
        }
        if (threadIdx.x == 0) out[0] = red[0];
    }
}

// ---------------------------------------------------------------- launch
extern "C" void kernel_launch(void* const* d_in, const int* in_sizes, int n_in,
                              void* d_out, int out_size) {
    const float* X = (const float*)d_in[0];
    const float* Y = (const float*)d_in[1];
    int N = in_sizes[0] / 16;
    int M = in_sizes[1] / 16;

    static int configured = 0;
    if (!configured) {
        cudaFuncSetAttribute(pair_mma_kernel,
                             cudaFuncAttributeMaxDynamicSharedMemorySize,
                             SM_TOT);
        configured = 1;
    }

    prep_kernel<<<128, 128>>>(Y, N, M);

    dim3 grid(M / 1024, N / 128);
    pair_mma_kernel<<<grid, 256, SM_TOT>>>(X);

    finalize_kernel<<<128, 256>>>(N, M, (float*)d_out);
}

// round 14
// speedup vs baseline: 1.5827x; 1.1345x over previous
#include <cuda_runtime.h>
#include <cuda_fp16.h>
#include <cstdint>

// ============================================================================
// Hyperbolic averaged Hausdorff loss via tensor-core mma.sync (fp16).
// (build targets plain sm_103: tcgen05 unavailable; legacy HMMA path)
//
// R14 = R13 with the bf16 3-term split replaced by an fp16 2-term split:
//   x' = x*invx, y' = y*invy;  xh = fp16(x'), xl = fp16(x' - xh)
//   acc = xh.yh + xl.yh + fold  (dropped xh.yl ~ 2^-11 relative, random sign;
//   output is a mean of 32768 mins -> final error ~1e-5)
//   A: [xh(16) | xl(16) | Ph,Ph,Pl,Qh,Qh,Ql | 0...]   P=xn*invx, Q=invx
//   B: [yh(16) | yh(16) | Ch,Cl,Ch,Dh,Dl,Dh | 0...]   C=-invy/2, D=-yn*invy/2
//   acc = invx*invy*(dot - (xn+yn)/2) = -sqdist*invx*invy/2
//   u = 1 - 4*acc (monotone) -> row/col mins are plain max(acc).
// K-units: 2 x k16 + 1 x k8 = 2.5 (was 3.5) -> tensor-pipe time -28.6%.
// ============================================================================

#define NPTS 16384
#define TILES_PER_SWEEP 8

__device__ int   g_rowmin[NPTS], g_colmin[NPTS];
__device__ float g_part[128];
__device__ int   g_done;
__device__ __half g_B[NPTS * 64];

__device__ __forceinline__ uint32_t smem_u32(const void* p) {
    uint32_t a;
    asm("{ .reg .u64 t; cvta.to.shared.u64 t, %1; cvt.u32.u64 %0, t; }"
        : "=r"(a) : "l"(p));
    return a;
}
#define SMEM_SWZ(o) ((o) ^ ((((o) >> 3) & 0x70)))

#define CPASYNC16(dst, src) \
    asm volatile("cp.async.cg.shared.global [%0], [%1], 16;" \
                 :: "r"(dst), "l"(src))
#define CPCOMMIT() asm volatile("cp.async.commit_group;")
#define CPWAIT0()  asm volatile("cp.async.wait_group 0;")

#define LDSM4(r, addr)                                                      \
    asm volatile("ldmatrix.sync.aligned.m8n8.x4.shared.b16 "                \
                 "{%0,%1,%2,%3}, [%4];"                                     \
                 : "=r"((r)[0]), "=r"((r)[1]), "=r"((r)[2]), "=r"((r)[3])   \
                 : "r"(addr))

#define MMA16816(d, a, b0, b1)                                              \
    asm volatile("mma.sync.aligned.m16n8k16.row.col.f32.f16.f16.f32 "      \
                 "{%0,%1,%2,%3}, {%4,%5,%6,%7}, {%8,%9}, {%0,%1,%2,%3};"    \
                 : "+f"((d)[0]), "+f"((d)[1]), "+f"((d)[2]), "+f"((d)[3])   \
                 : "r"((a)[0]), "r"((a)[1]), "r"((a)[2]), "r"((a)[3]),      \
                   "r"(b0), "r"(b1))

#define MMA16808(d, a0, a1, b0)                                             \
    asm volatile("mma.sync.aligned.m16n8k8.row.col.f32.f16.f16.f32 "       \
                 "{%0,%1,%2,%3}, {%4,%5}, {%6}, {%0,%1,%2,%3};"             \
                 : "+f"((d)[0]), "+f"((d)[1]), "+f"((d)[2]), "+f"((d)[3])   \
                 : "r"(a0), "r"(a1), "r"(b0))

// ---------------------------------------------------------------- smem layout
#define SM_A    0                       // 16384   (128 rows x 128B)
#define SM_B    16384                   // 2 x 16384 -> ends 49152
#define SM_ROW  49152                   // 2 x 128 x f32 = 1024
#define SM_TOT  50176

// --------------------------------------------------------------- split helpers
union HU { __half h; unsigned short u; };
__device__ __forceinline__ unsigned short hfu(float x) {
    HU t; t.h = __float2half_rn(x); return t.u;
}
__device__ __forceinline__ float hff(unsigned short u) {
    HU t; t.u = u; return __half2float(t.h);
}

// Build the 64-col fp16 row (w[32] packed pairs) for one point.
// A layout: [xh(16) | xl(16) | Ph,Ph,Pl,Qh,Qh,Ql | 0...]
// B layout: [yh(16) | yh(16) | Ch,Cl,Ch,Dh,Dl,Dh | 0...]
__device__ __forceinline__ void build_row(const float* __restrict__ src,
                                          bool isA, uint32_t* w) {
    float v[16];
    const float4* p = (const float4*)src;
    float4 q0 = p[0], q1 = p[1], q2 = p[2], q3 = p[3];
    v[0]=q0.x; v[1]=q0.y; v[2]=q0.z; v[3]=q0.w;
    v[4]=q1.x; v[5]=q1.y; v[6]=q1.z; v[7]=q1.w;
    v[8]=q2.x; v[9]=q2.y; v[10]=q2.z; v[11]=q2.w;
    v[12]=q3.x; v[13]=q3.y; v[14]=q3.z; v[15]=q3.w;
    float s = 0.f;
#pragma unroll
    for (int d = 0; d < 16; d++) s += v[d] * v[d];
    float inv = 1.0f / (1.0f - s);
#pragma unroll
    for (int d = 0; d < 16; d++) v[d] *= inv;

    unsigned short hi[16], lo[16];
#pragma unroll
    for (int d = 0; d < 16; d++) {
        hi[d] = hfu(v[d]);
        lo[d] = hfu(v[d] - hff(hi[d]));
    }
#pragma unroll
    for (int k = 0; k < 8; k++) {
        uint32_t hp = (uint32_t)hi[2*k] | ((uint32_t)hi[2*k+1] << 16);
        uint32_t lp = (uint32_t)lo[2*k] | ((uint32_t)lo[2*k+1] << 16);
        w[k]     = hp;
        w[8 + k] = isA ? lp : hp;
    }
    // fold cols 32..37 (pairs w[16..18]):
    //  A: (Ph,Ph),(Pl,Qh),(Qh,Ql)   B: (Ch,Cl),(Ch,Dh),(Dl,Dh)
    //  sum = Ph*Ch + Ph*Cl + Pl*Ch + Qh*Dh + Qh*Dl + Ql*Dh = P*C + Q*D
    if (isA) {
        float P = s * inv;
        unsigned short Ph = hfu(P), Pl = hfu(P - hff(Ph));
        unsigned short Qh = hfu(inv), Ql = hfu(inv - hff(Qh));
        w[16] = (uint32_t)Ph | ((uint32_t)Ph << 16);
        w[17] = (uint32_t)Pl | ((uint32_t)Qh << 16);
        w[18] = (uint32_t)Qh | ((uint32_t)Ql << 16);
    } else {
        float C = -0.5f * inv;
        unsigned short Ch = hfu(C), Cl = hfu(C - hff(Ch));
        float D = -0.5f * s * inv;
        unsigned short Dh = hfu(D), Dl = hfu(D - hff(Dh));
        w[16] = (uint32_t)Ch | ((uint32_t)Cl << 16);
        w[17] = (uint32_t)Ch | ((uint32_t)Dh << 16);
        w[18] = (uint32_t)Dl | ((uint32_t)Dh << 16);
    }
#pragma unroll
    for (int k = 19; k < 32; k++) w[k] = 0u;
}

// ---------------------------------------------------------------- prep kernel
// Y-only: 128 blocks x 128 threads.
__global__ void prep_kernel(const float* __restrict__ Y, int N, int M) {
    int idx = blockIdx.x * 128 + threadIdx.x;
    if (idx == 0) g_done = 0;
    if (idx < N) g_rowmin[idx] = 0x7f800000;
    if (idx < M) {
        g_colmin[idx] = 0x7f800000;
        uint32_t w[32];
        build_row(Y + (size_t)idx * 16, false, w);
        uint4* d4 = (uint4*)(g_B + (size_t)idx * 64);
#pragma unroll
        for (int c = 0; c < 8; c++)
            d4[c] = make_uint4(w[4*c], w[4*c+1], w[4*c+2], w[4*c+3]);
    }
}

// ---------------------------------------------------------------- pair kernel
__global__ void __launch_bounds__(256, 2) pair_mma_kernel(
        const float* __restrict__ X) {
    extern __shared__ __align__(16) char smem[];
    const uint32_t sb = smem_u32(smem);

    const int tid  = threadIdx.x;
    const int wid  = tid >> 5;
    const int lane = tid & 31;
    const int i0   = blockIdx.y * 128;
    const int jc0  = blockIdx.x * 1024;          // chunk base column

    const int wr = wid & 3;
    const int wc = wid >> 2;
    const int lr = lane & 15;
    const int lc = lane >> 4;
    const float NINF = __int_as_float(0xff800000);

    const int cr = tid >> 3, cc = tid & 7;       // 16B-chunk coords (4/thread)
    const uint32_t swz0 = SMEM_SWZ(cr * 128 + cc * 16);
    const uint32_t swz1 = SMEM_SWZ((cr + 32) * 128 + cc * 16);
    const uint32_t swz2 = SMEM_SWZ((cr + 64) * 128 + cc * 16);
    const uint32_t swz3 = SMEM_SWZ((cr + 96) * 128 + cc * 16);
    const size_t   goff = (size_t)cr * 128 + cc * 16;

    // ---- prologue: async-copy B tile 0; A tile computed from X in-place
    {
        const char* Bg = (const char*)g_B + (size_t)jc0 * 128;
        CPASYNC16(sb + SM_B + swz0, Bg + goff);
        CPASYNC16(sb + SM_B + swz1, Bg + goff + 32 * 128);
        CPASYNC16(sb + SM_B + swz2, Bg + goff + 64 * 128);
        CPASYNC16(sb + SM_B + swz3, Bg + goff + 96 * 128);
        CPCOMMIT();
    }
    if (tid < 128) {
        uint32_t w[32];
        build_row(X + (size_t)(i0 + tid) * 16, true, w);
#pragma unroll
        for (int c = 0; c < 8; c++)
            *(uint4*)(smem + SM_A + SMEM_SWZ(tid * 128 + c * 16)) =
                make_uint4(w[4*c], w[4*c+1], w[4*c+2], w[4*c+3]);
    }

    CPWAIT0();
    __syncthreads();

    // ---- A fragments once per sweep: 2 k16 steps + 1 k8 fold step
    uint32_t afr[2][2][4];
#pragma unroll
    for (int ks = 0; ks < 2; ks++)
#pragma unroll
        for (int mt = 0; mt < 2; mt++) {
            int row = 32*wr + 16*mt + lr;
            LDSM4(afr[ks][mt], sb + SM_A + SMEM_SWZ(row*128 + ks*32 + lc*16));
        }
    uint32_t afr8[4];    // fold cols 32..39 (byte offset 64)
    LDSM4(afr8, sb + SM_A + SMEM_SWZ((32*wr + lane)*128 + 64));

    // prefetch B tile 1
    {
        const char* Bg = (const char*)g_B + (size_t)(jc0 + 128) * 128;
        uint32_t d = sb + SM_B + 16384;
        CPASYNC16(d + swz0, Bg + goff);
        CPASYNC16(d + swz1, Bg + goff + 32 * 128);
        CPASYNC16(d + swz2, Bg + goff + 64 * 128);
        CPASYNC16(d + swz3, Bg + goff + 96 * 128);
        CPCOMMIT();
    }

    float rmax[4] = {NINF, NINF, NINF, NINF};

    const int b16 = (lane >> 4) & 1;
    const int b8  = (lane >> 3) & 1;
    const int b4  = (lane >> 2) & 1;
    const int ownCol = 8 * (2 * b16 + b8) + 2 * (lane & 3) + b4;

#pragma unroll 1
    for (int t = 0; t < TILES_PER_SWEEP; t++) {
        if (t > 0) {
            CPWAIT0();
            __syncthreads();
            if (t + 1 < TILES_PER_SWEEP) {
                const char* Bg =
                    (const char*)g_B + (size_t)(jc0 + (t + 1) * 128) * 128;
                uint32_t d = sb + SM_B + ((t + 1) & 1) * 16384;
                CPASYNC16(d + swz0, Bg + goff);
                CPASYNC16(d + swz1, Bg + goff + 32 * 128);
                CPASYNC16(d + swz2, Bg + goff + 64 * 128);
                CPASYNC16(d + swz3, Bg + goff + 96 * 128);
                CPCOMMIT();
            }
        }

        const uint32_t sBb = sb + SM_B + (t & 1) * 16384;
        const int jt = t * 128;

#pragma unroll
        for (int h = 0; h < 2; h++) {
            float acc[2][4][4];
#pragma unroll
            for (int mt = 0; mt < 2; mt++)
#pragma unroll
                for (int nt = 0; nt < 4; nt++)
#pragma unroll
                    for (int e = 0; e < 4; e++) acc[mt][nt][e] = 0.0f;

            // 2 k16 steps over data cols 0..31
#pragma unroll
            for (int ks = 0; ks < 2; ks++) {
                uint32_t b[2][4];
#pragma unroll
                for (int np = 0; np < 2; np++) {
                    int row = 64*wc + 32*h + 16*np + lr;
                    LDSM4(b[np], sBb + SMEM_SWZ(row*128 + ks*32 + lc*16));
                }
#pragma unroll
                for (int mt = 0; mt < 2; mt++)
#pragma unroll
                    for (int nt = 0; nt < 4; nt++) {
                        int np = nt >> 1, od = nt & 1;
                        MMA16816(acc[mt][nt], afr[ks][mt], b[np][od], b[np][od+2]);
                    }
            }
            // k8 fold step over cols 32..39 (half tensor occupancy)
            {
                uint32_t bf8[4];
                LDSM4(bf8, sBb + SMEM_SWZ((64*wc + 32*h + lane)*128 + 64));
#pragma unroll
                for (int mt = 0; mt < 2; mt++)
#pragma unroll
                    for (int nt = 0; nt < 4; nt++)
                        MMA16808(acc[mt][nt], afr8[2*mt], afr8[2*mt+1], bf8[nt]);
            }

            // ---- epilogue: 2 FMNMX per element, zero MULs
            float v[8];
#pragma unroll
            for (int k = 0; k < 8; k++) v[k] = NINF;
#pragma unroll
            for (int mt = 0; mt < 2; mt++)
#pragma unroll
                for (int nt = 0; nt < 4; nt++) {
                    float* c = acc[mt][nt];
                    rmax[2*mt]   = fmaxf(rmax[2*mt],   fmaxf(c[0], c[1]));
                    rmax[2*mt+1] = fmaxf(rmax[2*mt+1], fmaxf(c[2], c[3]));
                    v[2*nt]   = fmaxf(v[2*nt],   fmaxf(c[0], c[2]));
                    v[2*nt+1] = fmaxf(v[2*nt+1], fmaxf(c[1], c[3]));
                }

            // ---- reduce-scatter col MAX across the 8 duplicate lanes
#pragma unroll
            for (int q = 0; q < 4; q++) {
                float x = b16 ? v[q] : v[q + 4];
                float r = __shfl_xor_sync(0xffffffffu, x, 16);
                if (b16) v[q + 4] = fmaxf(v[q + 4], r);
                else     v[q]     = fmaxf(v[q], r);
            }
#pragma unroll
            for (int g = 0; g < 8; g += 4)
#pragma unroll
                for (int q = 0; q < 2; q++) {
                    float x = b8 ? v[g + q] : v[g + q + 2];
                    float r = __shfl_xor_sync(0xffffffffu, x, 8);
                    if (b8) v[g + q + 2] = fmaxf(v[g + q + 2], r);
                    else    v[g + q]     = fmaxf(v[g + q], r);
                }
#pragma unroll
            for (int g = 0; g < 8; g += 2) {
                float x = b4 ? v[g] : v[g + 1];
                float r = __shfl_xor_sync(0xffffffffu, x, 4);
                if (b4) v[g + 1] = fmaxf(v[g + 1], r);
                else    v[g]     = fmaxf(v[g], r);
            }
            float owned = b16 ? (b8 ? (b4 ? v[7] : v[6]) : (b4 ? v[5] : v[4]))
                              : (b8 ? (b4 ? v[3] : v[2]) : (b4 ? v[1] : v[0]));
            atomicMin(&g_colmin[jc0 + jt + 64*wc + 32*h + ownCol],
                      __float_as_int(fmaxf(-owned, 0.0f)));
        }
    }

    // ---- sweep epilogue: row maxes -> clamped mins
    float* rowp = (float*)(smem + SM_ROW);       // [2][128]
#pragma unroll
    for (int k = 0; k < 4; k++) {
        float v = rmax[k];
        v = fmaxf(v, __shfl_xor_sync(0xffffffffu, v, 1));
        v = fmaxf(v, __shfl_xor_sync(0xffffffffu, v, 2));
        if ((lane & 3) == 0)
            rowp[wc*128 + 32*wr + 16*(k >> 1) + 8*(k & 1) + (lane >> 2)] = v;
    }
    __syncthreads();
    if (tid < 128) {
        float rv = fmaxf(rowp[tid], rowp[128 + tid]);
        atomicMin(&g_rowmin[i0 + tid], __float_as_int(fmaxf(-rv, 0.0f)));
    }
}

// ---------------------------------------------------------------- finalize
__global__ void finalize_kernel(int N, int M, float* out) {
    __shared__ float red[256];
    __shared__ int   lastFlag;
    int  b     = blockIdx.x;
    bool isRow = (b < 64);
    int  idx   = (isRow ? b : b - 64) * 256 + threadIdx.x;
    float val  = 0.0f;
    int   lim  = isRow ? N : M;
    if (idx < lim) {
        float m = fmaxf(__int_as_float(isRow ? g_rowmin[idx] : g_colmin[idx]),
                        0.0f);
        float u = fmaf(4.0f, m, 1.0f);
        val = logf(u + sqrtf(fmaxf(u * u - 1.0f, 0.0f)));
    }
    red[threadIdx.x] = val;
    __syncthreads();
    for (int s = 128; s > 0; s >>= 1) {
        if (threadIdx.x < s) red[threadIdx.x] += red[threadIdx.x + s];
        __syncthreads();
    }
    if (threadIdx.x == 0) {
        g_part[b] = red[0] * (isRow ? 1.0f / (float)N : 1.0f / (float)M);
        __threadfence();
        int t = atomicAdd(&g_done, 1);
        lastFlag = (t == 127);
    }
    __syncthreads();
    if (lastFlag) {
        red[threadIdx.x] = (threadIdx.x < 128) ? g_part[threadIdx.x] : 0.0f;
        __syncthreads();
        for (int s = 128; s > 0; s >>= 1) {
            if (threadIdx.x < s) red[threadIdx.x] += red[threadIdx.x + s];
            __syncthreads();
        }
        if (threadIdx.x == 0) out[0] = red[0];
    }
}

// ---------------------------------------------------------------- launch
extern "C" void kernel_launch(void* const* d_in, const int* in_sizes, int n_in,
                              void* d_out, int out_size) {
    const float* X = (const float*)d_in[0];
    const float* Y = (const float*)d_in[1];
    int N = in_sizes[0] / 16;
    int M = in_sizes[1] / 16;

    static int configured = 0;
    if (!configured) {
        cudaFuncSetAttribute(pair_mma_kernel,
                             cudaFuncAttributeMaxDynamicSharedMemorySize,
                             SM_TOT);
        configured = 1;
    }

    prep_kernel<<<128, 128>>>(Y, N, M);

    dim3 grid(M / 1024, N / 128);
    pair_mma_kernel<<<grid, 256, SM_TOT>>>(X);

    finalize_kernel<<<128, 256>>>(N, M, (float*)d_out);
}

// round 15
// speedup vs baseline: 1.9191x; 1.2125x over previous
#include <cuda_runtime.h>
#include <cuda_fp16.h>
#include <cstdint>

// ============================================================================
// Hyperbolic averaged Hausdorff loss via tensor-core mma.sync (fp16).
// (build targets plain sm_103: tcgen05 unavailable; legacy HMMA path)
//
// R15 = R14 with single-term fp16 data (dropped the xl correction step):
//   x' = x*invx, y' = y*invy; xh = fp16(x'), yh = fp16(y')
//   acc = xh.yh + fold = -sqdist*invx*invy/2 + O(1.4e-4) per-pair noise
//   (measured propagation law: per-pair noise averages out in the mean;
//    predicted final rel_err ~1e-6..5e-6, threshold 1e-3)
//   A: [xh(16) | Ph,Ph,Pl,Qh,Qh,Ql | 0,0]   P=xn*invx, Q=invx   (24 cols)
//   B: [yh(16) | Ch,Cl,Ch,Dh,Dl,Dh | 0,0]   C=-invy/2, D=-yn*invy/2
//   u = 1 - 4*acc (monotone) -> row/col mins are plain max(acc).
// K-units: 1 x k16 + 1 x k8 = 1.5 (was 2.5). B rows packed at 48B in gmem.
// ============================================================================

#define NPTS 16384
#define TILES_PER_SWEEP 8

__device__ int   g_rowmin[NPTS], g_colmin[NPTS];
__device__ float g_part[128];
__device__ int   g_done;
__device__ __half g_B[NPTS * 24];      // 48B per point (24 fp16 cols)

__device__ __forceinline__ uint32_t smem_u32(const void* p) {
    uint32_t a;
    asm("{ .reg .u64 t; cvta.to.shared.u64 t, %1; cvt.u32.u64 %0, t; }"
        : "=r"(a) : "l"(p));
    return a;
}
#define SMEM_SWZ(o) ((o) ^ ((((o) >> 3) & 0x70)))

#define CPASYNC16(dst, src) \
    asm volatile("cp.async.cg.shared.global [%0], [%1], 16;" \
                 :: "r"(dst), "l"(src))
#define CPCOMMIT() asm volatile("cp.async.commit_group;")
#define CPWAIT0()  asm volatile("cp.async.wait_group 0;")

#define LDSM4(r, addr)                                                      \
    asm volatile("ldmatrix.sync.aligned.m8n8.x4.shared.b16 "                \
                 "{%0,%1,%2,%3}, [%4];"                                     \
                 : "=r"((r)[0]), "=r"((r)[1]), "=r"((r)[2]), "=r"((r)[3])   \
                 : "r"(addr))

#define MMA16816(d, a, b0, b1)                                              \
    asm volatile("mma.sync.aligned.m16n8k16.row.col.f32.f16.f16.f32 "      \
                 "{%0,%1,%2,%3}, {%4,%5,%6,%7}, {%8,%9}, {%0,%1,%2,%3};"    \
                 : "+f"((d)[0]), "+f"((d)[1]), "+f"((d)[2]), "+f"((d)[3])   \
                 : "r"((a)[0]), "r"((a)[1]), "r"((a)[2]), "r"((a)[3]),      \
                   "r"(b0), "r"(b1))

#define MMA16808(d, a0, a1, b0)                                             \
    asm volatile("mma.sync.aligned.m16n8k8.row.col.f32.f16.f16.f32 "       \
                 "{%0,%1,%2,%3}, {%4,%5}, {%6}, {%0,%1,%2,%3};"             \
                 : "+f"((d)[0]), "+f"((d)[1]), "+f"((d)[2]), "+f"((d)[3])   \
                 : "r"(a0), "r"(a1), "r"(b0))

// ---------------------------------------------------------------- smem layout
// Tiles keep 128B row pitch for the SW128/ldmatrix layout; only the first 3
// 16B chunks of each row are populated (48B of data).
#define SM_A    0                       // 16384   (128 rows x 128B pitch)
#define SM_B    16384                   // 2 x 16384 -> ends 49152
#define SM_ROW  49152                   // 2 x 128 x f32 = 1024
#define SM_TOT  50176

// --------------------------------------------------------------- split helpers
union HU { __half h; unsigned short u; };
__device__ __forceinline__ unsigned short hfu(float x) {
    HU t; t.h = __float2half_rn(x); return t.u;
}
__device__ __forceinline__ float hff(unsigned short u) {
    HU t; t.u = u; return __half2float(t.h);
}

// Build the 24-col fp16 row (w[12] packed pairs = 48B) for one point.
// A: [xh(16) | Ph,Ph,Pl,Qh,Qh,Ql | 0,0]
// B: [yh(16) | Ch,Cl,Ch,Dh,Dl,Dh | 0,0]
// fold sum = Ph*Ch + Ph*Cl + Pl*Ch + Qh*Dh + Qh*Dl + Ql*Dh ~= P*C + Q*D
__device__ __forceinline__ void build_row(const float* __restrict__ src,
                                          bool isA, uint32_t* w) {
    float v[16];
    const float4* p = (const float4*)src;
    float4 q0 = p[0], q1 = p[1], q2 = p[2], q3 = p[3];
    v[0]=q0.x; v[1]=q0.y; v[2]=q0.z; v[3]=q0.w;
    v[4]=q1.x; v[5]=q1.y; v[6]=q1.z; v[7]=q1.w;
    v[8]=q2.x; v[9]=q2.y; v[10]=q2.z; v[11]=q2.w;
    v[12]=q3.x; v[13]=q3.y; v[14]=q3.z; v[15]=q3.w;
    float s = 0.f;
#pragma unroll
    for (int d = 0; d < 16; d++) s += v[d] * v[d];
    float inv = 1.0f / (1.0f - s);
#pragma unroll
    for (int d = 0; d < 16; d++) v[d] *= inv;

#pragma unroll
    for (int k = 0; k < 8; k++)
        w[k] = (uint32_t)hfu(v[2*k]) | ((uint32_t)hfu(v[2*k+1]) << 16);

    if (isA) {
        float P = s * inv;
        unsigned short Ph = hfu(P), Pl = hfu(P - hff(Ph));
        unsigned short Qh = hfu(inv), Ql = hfu(inv - hff(Qh));
        w[8]  = (uint32_t)Ph | ((uint32_t)Ph << 16);
        w[9]  = (uint32_t)Pl | ((uint32_t)Qh << 16);
        w[10] = (uint32_t)Qh | ((uint32_t)Ql << 16);
    } else {
        float C = -0.5f * inv;
        unsigned short Ch = hfu(C), Cl = hfu(C - hff(Ch));
        float D = -0.5f * s * inv;
        unsigned short Dh = hfu(D), Dl = hfu(D - hff(Dh));
        w[8]  = (uint32_t)Ch | ((uint32_t)Cl << 16);
        w[9]  = (uint32_t)Ch | ((uint32_t)Dh << 16);
        w[10] = (uint32_t)Dl | ((uint32_t)Dh << 16);
    }
    w[11] = 0u;
}

// ---------------------------------------------------------------- prep kernel
// Y-only: 128 blocks x 128 threads.
__global__ void prep_kernel(const float* __restrict__ Y, int N, int M) {
    int idx = blockIdx.x * 128 + threadIdx.x;
    if (idx == 0) g_done = 0;
    if (idx < N) g_rowmin[idx] = 0x7f800000;
    if (idx < M) {
        g_colmin[idx] = 0x7f800000;
        uint32_t w[12];
        build_row(Y + (size_t)idx * 16, false, w);
        uint4* d4 = (uint4*)(g_B + (size_t)idx * 24);
#pragma unroll
        for (int c = 0; c < 3; c++)
            d4[c] = make_uint4(w[4*c], w[4*c+1], w[4*c+2], w[4*c+3]);
    }
}

// ---------------------------------------------------------------- pair kernel
__global__ void __launch_bounds__(256, 2) pair_mma_kernel(
        const float* __restrict__ X) {
    extern __shared__ __align__(16) char smem[];
    const uint32_t sb = smem_u32(smem);

    const int tid  = threadIdx.x;
    const int wid  = tid >> 5;
    const int lane = tid & 31;
    const int i0   = blockIdx.y * 128;
    const int jc0  = blockIdx.x * 1024;          // chunk base column

    const int wr = wid & 3;
    const int wc = wid >> 2;
    const int lr = lane & 15;
    const int lc = lane >> 4;
    const float NINF = __int_as_float(0xff800000);

    // B tile = 384 16B chunks (3 per row, gmem pitch 48B; chunk k at byte 16k)
    const int k0 = tid;                  // chunks 0..255
    const int k1 = tid + 256;            // chunks 256..383 (tid < 128 only)
    const int r0c = k0 / 3, c0c = k0 - 3 * r0c;
    const int r1c = k1 / 3, c1c = k1 - 3 * r1c;
    const uint32_t bswz0 = SMEM_SWZ(r0c * 128 + c0c * 16);
    const uint32_t bswz1 = SMEM_SWZ(r1c * 128 + c1c * 16);
    const uint32_t bgof0 = (uint32_t)k0 * 16;
    const uint32_t bgof1 = (uint32_t)k1 * 16;

    // ---- prologue: async-copy B tile 0; A tile computed from X in-place
    {
        const char* Bg = (const char*)g_B + (size_t)jc0 * 48;
        CPASYNC16(sb + SM_B + bswz0, Bg + bgof0);
        if (tid < 128) CPASYNC16(sb + SM_B + bswz1, Bg + bgof1);
        CPCOMMIT();
    }
    if (tid < 128) {
        uint32_t w[12];
        build_row(X + (size_t)(i0 + tid) * 16, true, w);
#pragma unroll
        for (int c = 0; c < 3; c++)
            *(uint4*)(smem + SM_A + SMEM_SWZ(tid * 128 + c * 16)) =
                make_uint4(w[4*c], w[4*c+1], w[4*c+2], w[4*c+3]);
    }

    CPWAIT0();
    __syncthreads();

    // ---- A fragments once per sweep: 1 k16 step + 1 k8 fold step
    uint32_t afr[2][4];                  // [mt] data cols 0..15
#pragma unroll
    for (int mt = 0; mt < 2; mt++) {
        int row = 32*wr + 16*mt + lr;
        LDSM4(afr[mt], sb + SM_A + SMEM_SWZ(row*128 + lc*16));
    }
    uint32_t afr8[4];                    // fold cols 16..23 (byte offset 32)
    LDSM4(afr8, sb + SM_A + SMEM_SWZ((32*wr + lane)*128 + 32));

    // prefetch B tile 1
    {
        const char* Bg = (const char*)g_B + (size_t)(jc0 + 128) * 48;
        uint32_t d = sb + SM_B + 16384;
        CPASYNC16(d + bswz0, Bg + bgof0);
        if (tid < 128) CPASYNC16(d + bswz1, Bg + bgof1);
        CPCOMMIT();
    }

    float rmax[4] = {NINF, NINF, NINF, NINF};

    const int b16 = (lane >> 4) & 1;
    const int b8  = (lane >> 3) & 1;
    const int b4  = (lane >> 2) & 1;
    const int ownCol = 8 * (2 * b16 + b8) + 2 * (lane & 3) + b4;

#pragma unroll 1
    for (int t = 0; t < TILES_PER_SWEEP; t++) {
        if (t > 0) {
            CPWAIT0();
            __syncthreads();
            if (t + 1 < TILES_PER_SWEEP) {
                const char* Bg =
                    (const char*)g_B + (size_t)(jc0 + (t + 1) * 128) * 48;
                uint32_t d = sb + SM_B + ((t + 1) & 1) * 16384;
                CPASYNC16(d + bswz0, Bg + bgof0);
                if (tid < 128) CPASYNC16(d + bswz1, Bg + bgof1);
                CPCOMMIT();
            }
        }

        const uint32_t sBb = sb + SM_B + (t & 1) * 16384;
        const int jt = t * 128;

#pragma unroll
        for (int h = 0; h < 2; h++) {
            float acc[2][4][4];
#pragma unroll
            for (int mt = 0; mt < 2; mt++)
#pragma unroll
                for (int nt = 0; nt < 4; nt++)
#pragma unroll
                    for (int e = 0; e < 4; e++) acc[mt][nt][e] = 0.0f;

            // k16 data step (cols 0..15)
            {
                uint32_t b[2][4];
#pragma unroll
                for (int np = 0; np < 2; np++) {
                    int row = 64*wc + 32*h + 16*np + lr;
                    LDSM4(b[np], sBb + SMEM_SWZ(row*128 + lc*16));
                }
#pragma unroll
                for (int mt = 0; mt < 2; mt++)
#pragma unroll
                    for (int nt = 0; nt < 4; nt++) {
                        int np = nt >> 1, od = nt & 1;
                        MMA16816(acc[mt][nt], afr[mt], b[np][od], b[np][od+2]);
                    }
            }
            // k8 fold step (cols 16..23, half tensor occupancy)
            {
                uint32_t bf8[4];
                LDSM4(bf8, sBb + SMEM_SWZ((64*wc + 32*h + lane)*128 + 32));
#pragma unroll
                for (int mt = 0; mt < 2; mt++)
#pragma unroll
                    for (int nt = 0; nt < 4; nt++)
                        MMA16808(acc[mt][nt], afr8[2*mt], afr8[2*mt+1], bf8[nt]);
            }

            // ---- epilogue: 2 FMNMX per element, zero MULs
            float v[8];
#pragma unroll
            for (int k = 0; k < 8; k++) v[k] = NINF;
#pragma unroll
            for (int mt = 0; mt < 2; mt++)
#pragma unroll
                for (int nt = 0; nt < 4; nt++) {
                    float* c = acc[mt][nt];
                    rmax[2*mt]   = fmaxf(rmax[2*mt],   fmaxf(c[0], c[1]));
                    rmax[2*mt+1] = fmaxf(rmax[2*mt+1], fmaxf(c[2], c[3]));
                    v[2*nt]   = fmaxf(v[2*nt],   fmaxf(c[0], c[2]));
                    v[2*nt+1] = fmaxf(v[2*nt+1], fmaxf(c[1], c[3]));
                }

            // ---- reduce-scatter col MAX across the 8 duplicate lanes
#pragma unroll
            for (int q = 0; q < 4; q++) {
                float x = b16 ? v[q] : v[q + 4];
                float r = __shfl_xor_sync(0xffffffffu, x, 16);
                if (b16) v[q + 4] = fmaxf(v[q + 4], r);
                else     v[q]     = fmaxf(v[q], r);
            }
#pragma unroll
            for (int g = 0; g < 8; g += 4)
#pragma unroll
                for (int q = 0; q < 2; q++) {
                    float x = b8 ? v[g + q] : v[g + q + 2];
                    float r = __shfl_xor_sync(0xffffffffu, x, 8);
                    if (b8) v[g + q + 2] = fmaxf(v[g + q + 2], r);
                    else    v[g + q]     = fmaxf(v[g + q], r);
                }
#pragma unroll
            for (int g = 0; g < 8; g += 2) {
                float x = b4 ? v[g] : v[g + 1];
                float r = __shfl_xor_sync(0xffffffffu, x, 4);
                if (b4) v[g + 1] = fmaxf(v[g + 1], r);
                else    v[g]     = fmaxf(v[g], r);
            }
            float owned = b16 ? (b8 ? (b4 ? v[7] : v[6]) : (b4 ? v[5] : v[4]))
                              : (b8 ? (b4 ? v[3] : v[2]) : (b4 ? v[1] : v[0]));
            atomicMin(&g_colmin[jc0 + jt + 64*wc + 32*h + ownCol],
                      __float_as_int(fmaxf(-owned, 0.0f)));
        }
    }

    // ---- sweep epilogue: row maxes -> clamped mins
    float* rowp = (float*)(smem + SM_ROW);       // [2][128]
#pragma unroll
    for (int k = 0; k < 4; k++) {
        float v = rmax[k];
        v = fmaxf(v, __shfl_xor_sync(0xffffffffu, v, 1));
        v = fmaxf(v, __shfl_xor_sync(0xffffffffu, v, 2));
        if ((lane & 3) == 0)
            rowp[wc*128 + 32*wr + 16*(k >> 1) + 8*(k & 1) + (lane >> 2)] = v;
    }
    __syncthreads();
    if (tid < 128) {
        float rv = fmaxf(rowp[tid], rowp[128 + tid]);
        atomicMin(&g_rowmin[i0 + tid], __float_as_int(fmaxf(-rv, 0.0f)));
    }
}

// ---------------------------------------------------------------- finalize
__global__ void finalize_kernel(int N, int M, float* out) {
    __shared__ float red[256];
    __shared__ int   lastFlag;
    int  b     = blockIdx.x;
    bool isRow = (b < 64);
    int  idx   = (isRow ? b : b - 64) * 256 + threadIdx.x;
    float val  = 0.0f;
    int   lim  = isRow ? N : M;
    if (idx < lim) {
        float m = fmaxf(__int_as_float(isRow ? g_rowmin[idx] : g_colmin[idx]),
                        0.0f);
        float u = fmaf(4.0f, m, 1.0f);
        val = logf(u + sqrtf(fmaxf(u * u - 1.0f, 0.0f)));
    }
    red[threadIdx.x] = val;
    __syncthreads();
    for (int s = 128; s > 0; s >>= 1) {
        if (threadIdx.x < s) red[threadIdx.x] += red[threadIdx.x + s];
        __syncthreads();
    }
    if (threadIdx.x == 0) {
        g_part[b] = red[0] * (isRow ? 1.0f / (float)N : 1.0f / (float)M);
        __threadfence();
        int t = atomicAdd(&g_done, 1);
        lastFlag = (t == 127);
    }
    __syncthreads();
    if (lastFlag) {
        red[threadIdx.x] = (threadIdx.x < 128) ? g_part[threadIdx.x] : 0.0f;
        __syncthreads();
        for (int s = 128; s > 0; s >>= 1) {
            if (threadIdx.x < s) red[threadIdx.x] += red[threadIdx.x + s];
            __syncthreads();
        }
        if (threadIdx.x == 0) out[0] = red[0];
    }
}

// ---------------------------------------------------------------- launch
extern "C" void kernel_launch(void* const* d_in, const int* in_sizes, int n_in,
                              void* d_out, int out_size) {
    const float* X = (const float*)d_in[0];
    const float* Y = (const float*)d_in[1];
    int N = in_sizes[0] / 16;
    int M = in_sizes[1] / 16;

    static int configured = 0;
    if (!configured) {
        cudaFuncSetAttribute(pair_mma_kernel,
                             cudaFuncAttributeMaxDynamicSharedMemorySize,
                             SM_TOT);
        configured = 1;
    }

    prep_kernel<<<128, 128>>>(Y, N, M);

    dim3 grid(M / 1024, N / 128);
    pair_mma_kernel<<<grid, 256, SM_TOT>>>(X);

    finalize_kernel<<<128, 256>>>(N, M, (float*)d_out);
}

// round 16
// speedup vs baseline: 2.4256x; 1.2639x over previous
#include <cuda_runtime.h>
#include <cuda_fp16.h>
#include <cstdint>

// ============================================================================
// Hyperbolic averaged Hausdorff loss via tensor-core mma.sync (fp16 in/out).
// (build targets plain sm_103: tcgen05 unavailable; legacy HMMA path)
//
// R16 = R15 with fp16 accumulators and a packed max.f16x2 epilogue:
//   acc (f16x2 pairs) = -sqdist*invx*invy/2 ; u = 1 - 4*acc (monotone)
//   rows: 1 HMAX2 per 2 elements (acc pairs are pre-packed by the MMA)
//   cols: HMAX2(d0,d1) then accumulate -> 2 per 4 elements
//   packed reduce-scatter (4 shfl + 4 HMAX2 + selects per half)
// K-units: 1 x k16 + 1 x k8 = 1.5. B rows packed at 48B in gmem.
// ============================================================================

#define NPTS 16384
#define TILES_PER_SWEEP 8

__device__ int   g_rowmin[NPTS], g_colmin[NPTS];
__device__ float g_part[128];
__device__ int   g_done;
__device__ __half g_B[NPTS * 24];      // 48B per point (24 fp16 cols)

__device__ __forceinline__ uint32_t smem_u32(const void* p) {
    uint32_t a;
    asm("{ .reg .u64 t; cvta.to.shared.u64 t, %1; cvt.u32.u64 %0, t; }"
        : "=r"(a) : "l"(p));
    return a;
}
#define SMEM_SWZ(o) ((o) ^ ((((o) >> 3) & 0x70)))

#define CPASYNC16(dst, src) \
    asm volatile("cp.async.cg.shared.global [%0], [%1], 16;" \
                 :: "r"(dst), "l"(src))
#define CPCOMMIT() asm volatile("cp.async.commit_group;")
#define CPWAIT0()  asm volatile("cp.async.wait_group 0;")

#define LDSM4(r, addr)                                                      \
    asm volatile("ldmatrix.sync.aligned.m8n8.x4.shared.b16 "                \
                 "{%0,%1,%2,%3}, [%4];"                                     \
                 : "=r"((r)[0]), "=r"((r)[1]), "=r"((r)[2]), "=r"((r)[3])   \
                 : "r"(addr))

// fp16-accumulator MMAs (d = two f16x2 regs: d0={r, cols c,c+1}, d1={r+8})
#define MMA16816H(d, a, b0, b1)                                             \
    asm volatile("mma.sync.aligned.m16n8k16.row.col.f16.f16.f16.f16 "      \
                 "{%0,%1}, {%2,%3,%4,%5}, {%6,%7}, {%0,%1};"                \
                 : "+r"((d)[0]), "+r"((d)[1])                               \
                 : "r"((a)[0]), "r"((a)[1]), "r"((a)[2]), "r"((a)[3]),      \
                   "r"(b0), "r"(b1))

#define MMA16808H(d, a0, a1, b0)                                            \
    asm volatile("mma.sync.aligned.m16n8k8.row.col.f16.f16.f16.f16 "       \
                 "{%0,%1}, {%2,%3}, {%4}, {%0,%1};"                         \
                 : "+r"((d)[0]), "+r"((d)[1])                               \
                 : "r"(a0), "r"(a1), "r"(b0))

#define HMAX2(d, a, b) \
    asm("max.f16x2 %0, %1, %2;" : "=r"(d) : "r"(a), "r"(b))

#define H2_NINF 0xFC00FC00u

// ---------------------------------------------------------------- smem layout
#define SM_A    0                       // 16384   (128 rows x 128B pitch)
#define SM_B    16384                   // 2 x 16384 -> ends 49152
#define SM_ROW  49152                   // 2 x 128 x f32 = 1024
#define SM_TOT  50176

// --------------------------------------------------------------- split helpers
union HU { __half h; unsigned short u; };
__device__ __forceinline__ unsigned short hfu(float x) {
    HU t; t.h = __float2half_rn(x); return t.u;
}
__device__ __forceinline__ float hff(unsigned short u) {
    HU t; t.u = u; return __half2float(t.h);
}

// Build the 24-col fp16 row (w[12] packed pairs = 48B) for one point.
// A: [xh(16) | Ph,Ph,Pl,Qh,Qh,Ql | 0,0]   P=xn*invx, Q=invx
// B: [yh(16) | Ch,Cl,Ch,Dh,Dl,Dh | 0,0]   C=-invy/2, D=-yn*invy/2
__device__ __forceinline__ void build_row(const float* __restrict__ src,
                                          bool isA, uint32_t* w) {
    float v[16];
    const float4* p = (const float4*)src;
    float4 q0 = p[0], q1 = p[1], q2 = p[2], q3 = p[3];
    v[0]=q0.x; v[1]=q0.y; v[2]=q0.z; v[3]=q0.w;
    v[4]=q1.x; v[5]=q1.y; v[6]=q1.z; v[7]=q1.w;
    v[8]=q2.x; v[9]=q2.y; v[10]=q2.z; v[11]=q2.w;
    v[12]=q3.x; v[13]=q3.y; v[14]=q3.z; v[15]=q3.w;
    float s = 0.f;
#pragma unroll
    for (int d = 0; d < 16; d++) s += v[d] * v[d];
    float inv = 1.0f / (1.0f - s);
#pragma unroll
    for (int d = 0; d < 16; d++) v[d] *= inv;

#pragma unroll
    for (int k = 0; k < 8; k++)
        w[k] = (uint32_t)hfu(v[2*k]) | ((uint32_t)hfu(v[2*k+1]) << 16);

    if (isA) {
        float P = s * inv;
        unsigned short Ph = hfu(P), Pl = hfu(P - hff(Ph));
        unsigned short Qh = hfu(inv), Ql = hfu(inv - hff(Qh));
        w[8]  = (uint32_t)Ph | ((uint32_t)Ph << 16);
        w[9]  = (uint32_t)Pl | ((uint32_t)Qh << 16);
        w[10] = (uint32_t)Qh | ((uint32_t)Ql << 16);
    } else {
        float C = -0.5f * inv;
        unsigned short Ch = hfu(C), Cl = hfu(C - hff(Ch));
        float D = -0.5f * s * inv;
        unsigned short Dh = hfu(D), Dl = hfu(D - hff(Dh));
        w[8]  = (uint32_t)Ch | ((uint32_t)Cl << 16);
        w[9]  = (uint32_t)Ch | ((uint32_t)Dh << 16);
        w[10] = (uint32_t)Dl | ((uint32_t)Dh << 16);
    }
    w[11] = 0u;
}

// ---------------------------------------------------------------- prep kernel
// Y-only: 128 blocks x 128 threads.
__global__ void prep_kernel(const float* __restrict__ Y, int N, int M) {
    int idx = blockIdx.x * 128 + threadIdx.x;
    if (idx == 0) g_done = 0;
    if (idx < N) g_rowmin[idx] = 0x7f800000;
    if (idx < M) {
        g_colmin[idx] = 0x7f800000;
        uint32_t w[12];
        build_row(Y + (size_t)idx * 16, false, w);
        uint4* d4 = (uint4*)(g_B + (size_t)idx * 24);
#pragma unroll
        for (int c = 0; c < 3; c++)
            d4[c] = make_uint4(w[4*c], w[4*c+1], w[4*c+2], w[4*c+3]);
    }
}

// ---------------------------------------------------------------- pair kernel
__global__ void __launch_bounds__(256, 2) pair_mma_kernel(
        const float* __restrict__ X) {
    extern __shared__ __align__(16) char smem[];
    const uint32_t sb = smem_u32(smem);

    const int tid  = threadIdx.x;
    const int wid  = tid >> 5;
    const int lane = tid & 31;
    const int i0   = blockIdx.y * 128;
    const int jc0  = blockIdx.x * 1024;          // chunk base column

    const int wr = wid & 3;
    const int wc = wid >> 2;
    const int lr = lane & 15;
    const int lc = lane >> 4;

    // B tile = 384 16B chunks (3 per row, gmem pitch 48B)
    const int k0 = tid;
    const int k1 = tid + 256;
    const int r0c = k0 / 3, c0c = k0 - 3 * r0c;
    const int r1c = k1 / 3, c1c = k1 - 3 * r1c;
    const uint32_t bswz0 = SMEM_SWZ(r0c * 128 + c0c * 16);
    const uint32_t bswz1 = SMEM_SWZ(r1c * 128 + c1c * 16);
    const uint32_t bgof0 = (uint32_t)k0 * 16;
    const uint32_t bgof1 = (uint32_t)k1 * 16;

    // ---- prologue: async-copy B tile 0; A tile computed from X in-place
    {
        const char* Bg = (const char*)g_B + (size_t)jc0 * 48;
        CPASYNC16(sb + SM_B + bswz0, Bg + bgof0);
        if (tid < 128) CPASYNC16(sb + SM_B + bswz1, Bg + bgof1);
        CPCOMMIT();
    }
    if (tid < 128) {
        uint32_t w[12];
        build_row(X + (size_t)(i0 + tid) * 16, true, w);
#pragma unroll
        for (int c = 0; c < 3; c++)
            *(uint4*)(smem + SM_A + SMEM_SWZ(tid * 128 + c * 16)) =
                make_uint4(w[4*c], w[4*c+1], w[4*c+2], w[4*c+3]);
    }

    CPWAIT0();
    __syncthreads();

    // ---- A fragments once per sweep: 1 k16 step + 1 k8 fold step
    uint32_t afr[2][4];
#pragma unroll
    for (int mt = 0; mt < 2; mt++) {
        int row = 32*wr + 16*mt + lr;
        LDSM4(afr[mt], sb + SM_A + SMEM_SWZ(row*128 + lc*16));
    }
    uint32_t afr8[4];                    // fold cols 16..23 (byte offset 32)
    LDSM4(afr8, sb + SM_A + SMEM_SWZ((32*wr + lane)*128 + 32));

    // prefetch B tile 1
    {
        const char* Bg = (const char*)g_B + (size_t)(jc0 + 128) * 48;
        uint32_t d = sb + SM_B + 16384;
        CPASYNC16(d + bswz0, Bg + bgof0);
        if (tid < 128) CPASYNC16(d + bswz1, Bg + bgof1);
        CPCOMMIT();
    }

    uint32_t rp[4] = {H2_NINF, H2_NINF, H2_NINF, H2_NINF};  // packed row maxes

    const int b16 = (lane >> 4) & 1;
    const int b8  = (lane >> 3) & 1;
    const int b4  = (lane >> 2) & 1;
    // lane's owned column after packed reduce-scatter
    const int ownCol = 8 * (2 * b16 + b8) + 2 * (lane & 3) + b4;

#pragma unroll 1
    for (int t = 0; t < TILES_PER_SWEEP; t++) {
        if (t > 0) {
            CPWAIT0();
            __syncthreads();
            if (t + 1 < TILES_PER_SWEEP) {
                const char* Bg =
                    (const char*)g_B + (size_t)(jc0 + (t + 1) * 128) * 48;
                uint32_t d = sb + SM_B + ((t + 1) & 1) * 16384;
                CPASYNC16(d + bswz0, Bg + bgof0);
                if (tid < 128) CPASYNC16(d + bswz1, Bg + bgof1);
                CPCOMMIT();
            }
        }

        const uint32_t sBb = sb + SM_B + (t & 1) * 16384;
        const int jt = t * 128;

#pragma unroll
        for (int h = 0; h < 2; h++) {
            uint32_t acc[2][4][2];       // [mt][nt][d0,d1] f16x2 pairs
#pragma unroll
            for (int mt = 0; mt < 2; mt++)
#pragma unroll
                for (int nt = 0; nt < 4; nt++) {
                    acc[mt][nt][0] = 0u;
                    acc[mt][nt][1] = 0u;
                }

            // k16 data step (cols 0..15)
            {
                uint32_t b[2][4];
#pragma unroll
                for (int np = 0; np < 2; np++) {
                    int row = 64*wc + 32*h + 16*np + lr;
                    LDSM4(b[np], sBb + SMEM_SWZ(row*128 + lc*16));
                }
#pragma unroll
                for (int mt = 0; mt < 2; mt++)
#pragma unroll
                    for (int nt = 0; nt < 4; nt++) {
                        int np = nt >> 1, od = nt & 1;
                        MMA16816H(acc[mt][nt], afr[mt], b[np][od], b[np][od+2]);
                    }
            }
            // k8 fold step (cols 16..23)
            {
                uint32_t bf8[4];
                LDSM4(bf8, sBb + SMEM_SWZ((64*wc + 32*h + lane)*128 + 32));
#pragma unroll
                for (int mt = 0; mt < 2; mt++)
#pragma unroll
                    for (int nt = 0; nt < 4; nt++)
                        MMA16808H(acc[mt][nt], afr8[2*mt], afr8[2*mt+1], bf8[nt]);
            }

            // ---- epilogue: 1 HMAX2 per 2 elements
            uint32_t vp[4] = {H2_NINF, H2_NINF, H2_NINF, H2_NINF};
#pragma unroll
            for (int mt = 0; mt < 2; mt++)
#pragma unroll
                for (int nt = 0; nt < 4; nt++) {
                    uint32_t* c = acc[mt][nt];
                    HMAX2(rp[2*mt],   rp[2*mt],   c[0]);
                    HMAX2(rp[2*mt+1], rp[2*mt+1], c[1]);
                    uint32_t tm;
                    HMAX2(tm, c[0], c[1]);
                    HMAX2(vp[nt], vp[nt], tm);
                }

            // ---- packed reduce-scatter of col maxes over 8 duplicate lanes
            // L1 (xor16): b16=0 keeps vp[0..1], b16=1 keeps vp[2..3]
#pragma unroll
            for (int q = 0; q < 2; q++) {
                uint32_t x = b16 ? vp[q] : vp[q + 2];
                uint32_t r = __shfl_xor_sync(0xffffffffu, x, 16);
                if (b16) { HMAX2(vp[q + 2], vp[q + 2], r); }
                else     { HMAX2(vp[q], vp[q], r); }
            }
            uint32_t va = b16 ? vp[2] : vp[0];
            uint32_t vb = b16 ? vp[3] : vp[1];
            // L2 (xor8): keep (b8 ? vb : va)
            {
                uint32_t s2   = b8 ? va : vb;
                uint32_t keep = b8 ? vb : va;
                uint32_t r2 = __shfl_xor_sync(0xffffffffu, s2, 8);
                uint32_t L;
                HMAX2(L, keep, r2);
                // L3 (xor4): both b4 partners end with the complete pair
                uint32_t r3 = __shfl_xor_sync(0xffffffffu, L, 4);
                uint32_t F;
                HMAX2(F, L, r3);
                __half2 hf = *reinterpret_cast<__half2*>(&F);
                float owned = b4 ? __high2float(hf) : __low2float(hf);
                atomicMin(&g_colmin[jc0 + jt + 64*wc + 32*h + ownCol],
                          __float_as_int(fmaxf(-owned, 0.0f)));
            }
        }
    }

    // ---- sweep epilogue: row maxes -> clamped mins
    float* rowp = (float*)(smem + SM_ROW);       // [2][128]
#pragma unroll
    for (int k = 0; k < 4; k++) {
        __half2 h2 = *reinterpret_cast<__half2*>(&rp[k]);
        float v = fmaxf(__low2float(h2), __high2float(h2));
        v = fmaxf(v, __shfl_xor_sync(0xffffffffu, v, 1));
        v = fmaxf(v, __shfl_xor_sync(0xffffffffu, v, 2));
        if ((lane & 3) == 0)
            rowp[wc*128 + 32*wr + 16*(k >> 1) + 8*(k & 1) + (lane >> 2)] = v;
    }
    __syncthreads();
    if (tid < 128) {
        float rv = fmaxf(rowp[tid], rowp[128 + tid]);
        atomicMin(&g_rowmin[i0 + tid], __float_as_int(fmaxf(-rv, 0.0f)));
    }
}

// ---------------------------------------------------------------- finalize
__global__ void finalize_kernel(int N, int M, float* out) {
    __shared__ float red[256];
    __shared__ int   lastFlag;
    int  b     = blockIdx.x;
    bool isRow = (b < 64);
    int  idx   = (isRow ? b : b - 64) * 256 + threadIdx.x;
    float val  = 0.0f;
    int   lim  = isRow ? N : M;
    if (idx < lim) {
        float m = fmaxf(__int_as_float(isRow ? g_rowmin[idx] : g_colmin[idx]),
                        0.0f);
        float u = fmaf(4.0f, m, 1.0f);
        val = logf(u + sqrtf(fmaxf(u * u - 1.0f, 0.0f)));
    }
    red[threadIdx.x] = val;
    __syncthreads();
    for (int s = 128; s > 0; s >>= 1) {
        if (threadIdx.x < s) red[threadIdx.x] += red[threadIdx.x + s];
        __syncthreads();
    }
    if (threadIdx.x == 0) {
        g_part[b] = red[0] * (isRow ? 1.0f / (float)N : 1.0f / (float)M);
        __threadfence();
        int t = atomicAdd(&g_done, 1);
        lastFlag = (t == 127);
    }
    __syncthreads();
    if (lastFlag) {
        red[threadIdx.x] = (threadIdx.x < 128) ? g_part[threadIdx.x] : 0.0f;
        __syncthreads();
        for (int s = 128; s > 0; s >>= 1) {
            if (threadIdx.x < s) red[threadIdx.x] += red[threadIdx.x + s];
            __syncthreads();
        }
        if (threadIdx.x == 0) out[0] = red[0];
    }
}

// ---------------------------------------------------------------- launch
extern "C" void kernel_launch(void* const* d_in, const int* in_sizes, int n_in,
                              void* d_out, int out_size) {
    const float* X = (const float*)d_in[0];
    const float* Y = (const float*)d_in[1];
    int N = in_sizes[0] / 16;
    int M = in_sizes[1] / 16;

    static int configured = 0;
    if (!configured) {
        cudaFuncSetAttribute(pair_mma_kernel,
                             cudaFuncAttributeMaxDynamicSharedMemorySize,
                             SM_TOT);
        configured = 1;
    }

    prep_kernel<<<128, 128>>>(Y, N, M);

    dim3 grid(M / 1024, N / 128);
    pair_mma_kernel<<<grid, 256, SM_TOT>>>(X);

    finalize_kernel<<<128, 256>>>(N, M, (float*)d_out);
}